// round 5
// baseline (speedup 1.0000x reference)
#include <cuda_runtime.h>
#include <math.h>
#include <stdint.h>

// ---------------- problem constants ----------------
#define B_    2
#define S_    2048
#define HID_  2048
#define IN_   4096
#define H_    16
#define NOPE_ 128
#define ROPE_ 64
#define VHD_  128
#define QKD_  192
#define QR_   1536
#define KVR_  512
#define TOK_  (B_*S_)
#define BH_   (B_*H_)
#define EPS_  1e-6f

// ---------------- scratch ----------------
__device__ float g_qa [TOK_*QR_];
__device__ float g_q  [TOK_*(H_*QKD_)];
__device__ float g_kvc[TOK_*(KVR_+ROPE_)];
__device__ float g_kvn[TOK_*KVR_];
__device__ float g_kv [TOK_*(H_*(NOPE_+VHD_))];
__device__ float g_Qf [BH_*S_*QKD_];
__device__ float g_Kf [BH_*S_*QKD_];
__device__ float g_Vf [BH_*S_*VHD_];
__device__ float g_Sc [(size_t)BH_*S_*S_];
__device__ float g_ctx[TOK_*(H_*VHD_)];
__device__ float g_cos[TOK_*32];
__device__ float g_sin[TOK_*32];
// tf32-rounded copies of harness inputs
__device__ float g_hsc [TOK_*IN_];
__device__ float g_wqa [IN_*QR_];
__device__ float g_wqb [QR_*(H_*QKD_)];
__device__ float g_wkva[IN_*(KVR_+ROPE_)];
__device__ float g_wkvb[KVR_*(H_*(NOPE_+VHD_))];
__device__ float g_wo  [HID_*HID_];

// ---------------- helpers ----------------
__device__ __forceinline__ uint32_t f2tf32(float x) {
    uint32_t u;
    asm("cvt.rna.tf32.f32 %0, %1;" : "=r"(u) : "f"(x));
    return u;
}
__device__ __forceinline__ float rnd32(float x) { return __uint_as_float(f2tf32(x)); }

__device__ __forceinline__ void mma_tf32(float c[4], const uint32_t a[4], const uint32_t b[2]) {
    asm volatile(
        "mma.sync.aligned.m16n8k8.row.col.f32.tf32.tf32.f32 "
        "{%0,%1,%2,%3}, {%4,%5,%6,%7}, {%8,%9}, {%0,%1,%2,%3};"
        : "+f"(c[0]), "+f"(c[1]), "+f"(c[2]), "+f"(c[3])
        : "r"(a[0]), "r"(a[1]), "r"(a[2]), "r"(a[3]), "r"(b[0]), "r"(b[1]));
}
__device__ __forceinline__ void cp16(uint32_t dst, const void* src, bool pred) {
    int sz = pred ? 16 : 0;
    asm volatile("cp.async.cg.shared.global [%0], [%1], 16, %2;\n"
                 :: "r"(dst), "l"(src), "r"(sz));
}
__device__ __forceinline__ void cp_commit() {
    asm volatile("cp.async.commit_group;\n" ::: "memory");
}
__device__ __forceinline__ void cp_wait2() {
    asm volatile("cp.async.wait_group 2;\n" ::: "memory");
}

// ---------------- tf32 tensor-core GEMM, cp.async 4-stage pipeline ----------------
// Inputs are PRE-ROUNDED to tf32 bit patterns -> no cvt in mainloop.
// C[M,N] = alpha * A[M,K] @ op(B);  op(B) = B[K,N] (TB=0) or B[N,K]^T (TB=1)
#define GBM 128
#define GBN 128
#define GBK 16
#define STAGES 4
#define A_LDK 20
#define B_LDN 136

#define A_STG (GBM*A_LDK)
#define BNN_STG (GBK*B_LDN)
#define BTB_STG (GBN*A_LDK)

template<bool TB, bool CAUSAL, bool PV>
__global__ __launch_bounds__(256, 2) void mma_gemm(
    const float* __restrict__ A, const float* __restrict__ B, float* __restrict__ C,
    int M, int N, int K, int lda, int ldb, int ldc,
    size_t sA, size_t sB, size_t sC, float alpha)
{
    if (CAUSAL && blockIdx.x > blockIdx.y) return;

    extern __shared__ float smem[];
    float* Asm = smem;
    float* Bsm = smem + STAGES * A_STG;
    const uint32_t sA32 = (uint32_t)__cvta_generic_to_shared(Asm);
    const uint32_t sB32 = (uint32_t)__cvta_generic_to_shared(Bsm);

    const int bz = blockIdx.z;
    A += (size_t)bz * sA;
    B += (size_t)bz * sB;
    size_t cOff;
    if (PV) cOff = (size_t)(bz / H_) * S_ * ldc + (size_t)(bz % H_) * VHD_;
    else    cOff = (size_t)bz * sC;

    const int Keff = PV ? min(K, (int)(blockIdx.y + 1) * GBM) : K;
    const int nt = Keff / GBK;

    const int tid  = threadIdx.x;
    const int lane = tid & 31;
    const int g    = lane >> 2;
    const int tig  = lane & 3;
    const int wid  = tid >> 5;
    const int wm   = wid & 1;
    const int wn   = wid >> 1;

    // ---- loader indices ----
    const int a_row = tid >> 1;
    const int a_k   = (tid & 1) << 3;
    const float* Ap = A + (size_t)(blockIdx.y * GBM + a_row) * lda + a_k;
    const uint32_t a_dst0 = sA32 + (uint32_t)(a_row * A_LDK + a_k) * 4u;

    const float* Bp;
    uint32_t b_dst0;
    bool bv0 = true, bv1 = true;
    if (TB) {
        const int b_n = tid >> 1;
        const int b_k = (tid & 1) << 3;
        bv0 = bv1 = (blockIdx.x * GBN + b_n) < N;
        Bp = B + (size_t)(blockIdx.x * GBN + b_n) * ldb + b_k;
        b_dst0 = sB32 + (uint32_t)(b_n * A_LDK + b_k) * 4u;
    } else {
        const int b_kr = tid >> 4;
        const int b_nc = (tid & 15) << 3;
        bv0 = (blockIdx.x * GBN + b_nc)     < N;
        bv1 = (blockIdx.x * GBN + b_nc + 4) < N;
        Bp = B + (size_t)b_kr * ldb + blockIdx.x * GBN + b_nc;
        b_dst0 = sB32 + (uint32_t)(b_kr * B_LDN + b_nc) * 4u;
    }

    auto load_stage = [&](int st, int k0) {
        uint32_t ad = a_dst0 + (uint32_t)(st * A_STG) * 4u;
        const float* as = Ap + k0;
        cp16(ad,      as,     true);
        cp16(ad + 16, as + 4, true);
        if (TB) {
            uint32_t bd = b_dst0 + (uint32_t)(st * BTB_STG) * 4u;
            const float* bs = Bp + k0;
            cp16(bd,      bs,     bv0);
            cp16(bd + 16, bs + 4, bv1);
        } else {
            uint32_t bd = b_dst0 + (uint32_t)(st * BNN_STG) * 4u;
            const float* bs = Bp + (size_t)k0 * ldb;
            cp16(bd,      bs,     bv0);
            cp16(bd + 16, bs + 4, bv1);
        }
    };

    float acc[4][4][4];
    #pragma unroll
    for (int i = 0; i < 4; i++)
        #pragma unroll
        for (int j = 0; j < 4; j++)
            #pragma unroll
            for (int r = 0; r < 4; r++) acc[i][j][r] = 0.f;

    // prologue: stages 0..2 (commit always to keep group counts consistent)
    #pragma unroll
    for (int s = 0; s < STAGES - 1; s++) {
        if (s < nt) load_stage(s, s * GBK);
        cp_commit();
    }

    for (int t = 0; t < nt; t++) {
        cp_wait2();
        __syncthreads();

        const int tn = t + STAGES - 1;
        if (tn < nt) load_stage(tn % STAGES, tn * GBK);
        cp_commit();

        const uint32_t* Ab = (const uint32_t*)(Asm + (t % STAGES) * A_STG);
        const uint32_t* Bb = (const uint32_t*)(TB ? (Bsm + (t % STAGES) * BTB_STG)
                                                  : (Bsm + (t % STAGES) * BNN_STG));

        #pragma unroll
        for (int ks = 0; ks < 2; ks++) {
            const int kb = ks * 8;
            uint32_t afr[4][4], bfr[4][2];
            #pragma unroll
            for (int fm = 0; fm < 4; fm++) {
                const int m = wm * 64 + fm * 16 + g;
                afr[fm][0] = Ab[(size_t)m       * A_LDK + kb + tig];
                afr[fm][1] = Ab[(size_t)(m + 8) * A_LDK + kb + tig];
                afr[fm][2] = Ab[(size_t)m       * A_LDK + kb + tig + 4];
                afr[fm][3] = Ab[(size_t)(m + 8) * A_LDK + kb + tig + 4];
            }
            #pragma unroll
            for (int fn = 0; fn < 4; fn++) {
                const int n = wn * 32 + fn * 8 + g;
                if (TB) {
                    bfr[fn][0] = Bb[(size_t)n * A_LDK + kb + tig];
                    bfr[fn][1] = Bb[(size_t)n * A_LDK + kb + tig + 4];
                } else {
                    bfr[fn][0] = Bb[(size_t)(kb + tig)     * B_LDN + n];
                    bfr[fn][1] = Bb[(size_t)(kb + tig + 4) * B_LDN + n];
                }
            }
            #pragma unroll
            for (int fm = 0; fm < 4; fm++)
                #pragma unroll
                for (int fn = 0; fn < 4; fn++)
                    mma_tf32(acc[fm][fn], afr[fm], bfr[fn]);
        }
    }

    // epilogue (PV output is consumed by another GEMM -> store tf32-rounded)
    #pragma unroll
    for (int fm = 0; fm < 4; fm++) {
        #pragma unroll
        for (int fn = 0; fn < 4; fn++) {
            const int row = blockIdx.y * GBM + wm * 64 + fm * 16 + g;
            const int col = blockIdx.x * GBN + wn * 32 + fn * 8 + tig * 2;
            if (col < N) {
                float v0 = acc[fm][fn][0] * alpha, v1 = acc[fm][fn][1] * alpha;
                float v2 = acc[fm][fn][2] * alpha, v3 = acc[fm][fn][3] * alpha;
                if (PV) { v0 = rnd32(v0); v1 = rnd32(v1); v2 = rnd32(v2); v3 = rnd32(v3); }
                *(float2*)&C[cOff + (size_t)row * ldc + col]       = make_float2(v0, v1);
                *(float2*)&C[cOff + (size_t)(row + 8) * ldc + col] = make_float2(v2, v3);
            }
        }
    }
}

#define SMEM_NN ((STAGES*A_STG + STAGES*BNN_STG) * 4)
#define SMEM_TB ((STAGES*A_STG + STAGES*BTB_STG) * 4)

// ---------------- tf32 convert pass (float4) ----------------
__global__ void cvt_pass(const float* __restrict__ src, float* __restrict__ dst, int n4) {
    int i = blockIdx.x * blockDim.x + threadIdx.x;
    if (i >= n4) return;
    float4 v = ((const float4*)src)[i];
    v.x = rnd32(v.x); v.y = rnd32(v.y); v.z = rnd32(v.z); v.w = rnd32(v.w);
    ((float4*)dst)[i] = v;
}

// ---------------- block reductions ----------------
__device__ __forceinline__ float block_reduce_max(float v, float* sbuf) {
    int tid = threadIdx.x;
    sbuf[tid] = v; __syncthreads();
    #pragma unroll
    for (int s = 128; s > 0; s >>= 1) {
        if (tid < s) sbuf[tid] = fmaxf(sbuf[tid], sbuf[tid + s]);
        __syncthreads();
    }
    float r = sbuf[0]; __syncthreads();
    return r;
}
__device__ __forceinline__ float block_reduce_sum(float v, float* sbuf) {
    int tid = threadIdx.x;
    sbuf[tid] = v; __syncthreads();
    #pragma unroll
    for (int s = 128; s > 0; s >>= 1) {
        if (tid < s) sbuf[tid] = sbuf[tid] + sbuf[tid + s];
        __syncthreads();
    }
    float r = sbuf[0]; __syncthreads();
    return r;
}

// ---------------- rmsnorm (output tf32-rounded) ----------------
__global__ __launch_bounds__(256) void rmsnorm_kernel(const float* __restrict__ x,
                                                      const float* __restrict__ w,
                                                      float* __restrict__ y,
                                                      int n, int si, int so)
{
    __shared__ float sbuf[256];
    const size_t row = blockIdx.x;
    const float* xr = x + row * si;
    float acc = 0.f;
    for (int j = threadIdx.x; j < n; j += 256) { float v = xr[j]; acc += v * v; }
    float tot = block_reduce_sum(acc, sbuf);
    float scale = rsqrtf(tot / (float)n + EPS_);
    float* yr = y + row * so;
    for (int j = threadIdx.x; j < n; j += 256) yr[j] = rnd32(xr[j] * scale * w[j]);
}

// ---------------- RoPE table + assembly (outputs tf32-rounded) ----------------
__global__ void build_cs(const int* __restrict__ pos) {
    int idx = blockIdx.x * blockDim.x + threadIdx.x;
    if (idx >= TOK_ * 32) return;
    int j = idx & 31, tok = idx >> 5;
    float inv = powf(10000.f, -((float)(2 * j)) / 64.f);
    float ang = (float)pos[tok] * inv;
    g_cos[idx] = cosf(ang);
    g_sin[idx] = sinf(ang);
}

__device__ __forceinline__ float rope_val(const float* pair_base, int drel, int tok) {
    int j = drel >> 1;
    float c = g_cos[tok * 32 + j], s = g_sin[tok * 32 + j];
    float ev = pair_base[2*j], ov = pair_base[2*j + 1];
    return ((drel & 1) == 0) ? (ev * c - ov * s) : (ov * c + ev * s);
}

__global__ void build_q() {
    int idx = blockIdx.x * blockDim.x + threadIdx.x;
    if (idx >= BH_ * S_ * QKD_) return;
    int d  = idx % QKD_;
    int r  = idx / QKD_;
    int s  = r % S_;
    int bh = r / S_;
    int b = bh / H_, h = bh % H_;
    int tok = b * S_ + s;
    const float* src = g_q + (size_t)tok * (H_*QKD_) + h * QKD_;
    float v;
    if (d < NOPE_) v = src[d];
    else           v = rope_val(src + NOPE_, d - NOPE_, tok);
    g_Qf[idx] = rnd32(v);
}

__global__ void build_k() {
    int idx = blockIdx.x * blockDim.x + threadIdx.x;
    if (idx >= BH_ * S_ * QKD_) return;
    int d  = idx % QKD_;
    int r  = idx / QKD_;
    int s  = r % S_;
    int bh = r / S_;
    int b = bh / H_, h = bh % H_;
    int tok = b * S_ + s;
    float v;
    if (d < NOPE_) v = g_kv[(size_t)tok * (H_*(NOPE_+VHD_)) + h * (NOPE_+VHD_) + d];
    else           v = rope_val(g_kvc + (size_t)tok * (KVR_+ROPE_) + KVR_, d - NOPE_, tok);
    g_Kf[idx] = rnd32(v);
}

__global__ void build_v() {
    int idx = blockIdx.x * blockDim.x + threadIdx.x;
    if (idx >= BH_ * S_ * VHD_) return;
    int d  = idx % VHD_;
    int r  = idx / VHD_;
    int s  = r % S_;
    int bh = r / S_;
    int b = bh / H_, h = bh % H_;
    int tok = b * S_ + s;
    g_Vf[idx] = rnd32(g_kv[(size_t)tok * (H_*(NOPE_+VHD_)) + h * (NOPE_+VHD_) + NOPE_ + d]);
}

// ---------------- causal softmax (probs stored tf32-rounded) ----------------
__global__ __launch_bounds__(256) void softmax_causal() {
    __shared__ float sbuf[256];
    const int row = blockIdx.x;
    const int q = row % S_;
    float* p = g_Sc + (size_t)row * S_;
    const int n = q + 1;

    float m = -INFINITY;
    for (int j = threadIdx.x; j < n; j += 256) m = fmaxf(m, p[j]);
    m = block_reduce_max(m, sbuf);

    float acc = 0.f;
    for (int j = threadIdx.x; j < n; j += 256) {
        float e = expf(p[j] - m);
        p[j] = e;
        acc += e;
    }
    float tot = block_reduce_sum(acc, sbuf);
    float inv = 1.f / tot;
    for (int j = threadIdx.x; j < n; j += 256) p[j] = rnd32(p[j] * inv);
    for (int j = n + threadIdx.x; j < S_; j += 256) p[j] = 0.f;
}

// ---------------- launcher ----------------
extern "C" void kernel_launch(void* const* d_in, const int* in_sizes, int n_in,
                              void* d_out, int out_size)
{
    const float* hs    = (const float*)d_in[0];
    const float* Wq_a  = (const float*)d_in[1];
    const float* q_ln  = (const float*)d_in[2];
    const float* Wq_b  = (const float*)d_in[3];
    const float* Wkv_a = (const float*)d_in[4];
    const float* kv_ln = (const float*)d_in[5];
    const float* Wkv_b = (const float*)d_in[6];
    const float* Wo    = (const float*)d_in[7];
    const int*   pos   = (const int*)  d_in[8];
    float* out = (float*)d_out;

    float *p_qa, *p_q, *p_kvc, *p_kvn, *p_kv, *p_ctx, *p_Qf, *p_Kf, *p_Vf, *p_Sc;
    float *p_hsc, *p_wqa, *p_wqb, *p_wkva, *p_wkvb, *p_wo;
    cudaGetSymbolAddress((void**)&p_qa,  g_qa);
    cudaGetSymbolAddress((void**)&p_q,   g_q);
    cudaGetSymbolAddress((void**)&p_kvc, g_kvc);
    cudaGetSymbolAddress((void**)&p_kvn, g_kvn);
    cudaGetSymbolAddress((void**)&p_kv,  g_kv);
    cudaGetSymbolAddress((void**)&p_ctx, g_ctx);
    cudaGetSymbolAddress((void**)&p_Qf,  g_Qf);
    cudaGetSymbolAddress((void**)&p_Kf,  g_Kf);
    cudaGetSymbolAddress((void**)&p_Vf,  g_Vf);
    cudaGetSymbolAddress((void**)&p_Sc,  g_Sc);
    cudaGetSymbolAddress((void**)&p_hsc,  g_hsc);
    cudaGetSymbolAddress((void**)&p_wqa,  g_wqa);
    cudaGetSymbolAddress((void**)&p_wqb,  g_wqb);
    cudaGetSymbolAddress((void**)&p_wkva, g_wkva);
    cudaGetSymbolAddress((void**)&p_wkvb, g_wkvb);
    cudaGetSymbolAddress((void**)&p_wo,   g_wo);

    static bool attr_done = false;
    if (!attr_done) {
        cudaFuncSetAttribute(mma_gemm<false,false,false>,
                             cudaFuncAttributeMaxDynamicSharedMemorySize, SMEM_NN);
        cudaFuncSetAttribute(mma_gemm<true,true,false>,
                             cudaFuncAttributeMaxDynamicSharedMemorySize, SMEM_TB);
        cudaFuncSetAttribute(mma_gemm<false,false,true>,
                             cudaFuncAttributeMaxDynamicSharedMemorySize, SMEM_NN);
        attr_done = true;
    }

    // tf32-round harness inputs (one pass each)
    cvt_pass<<<(TOK_*IN_/4 + 255)/256, 256>>>(hs, p_hsc, TOK_*IN_/4);
    cvt_pass<<<(IN_*QR_/4 + 255)/256, 256>>>(Wq_a, p_wqa, IN_*QR_/4);
    cvt_pass<<<(QR_*(H_*QKD_)/4 + 255)/256, 256>>>(Wq_b, p_wqb, QR_*(H_*QKD_)/4);
    cvt_pass<<<(IN_*(KVR_+ROPE_)/4 + 255)/256, 256>>>(Wkv_a, p_wkva, IN_*(KVR_+ROPE_)/4);
    cvt_pass<<<(KVR_*(H_*(NOPE_+VHD_))/4 + 255)/256, 256>>>(Wkv_b, p_wkvb, KVR_*(H_*(NOPE_+VHD_))/4);
    cvt_pass<<<(HID_*HID_/4 + 255)/256, 256>>>(Wo, p_wo, HID_*HID_/4);

    // q path
    mma_gemm<false,false,false><<<dim3(QR_/GBN, TOK_/GBM, 1), 256, SMEM_NN>>>(
        p_hsc, p_wqa, p_qa, TOK_, QR_, IN_, IN_, QR_, QR_, 0, 0, 0, 1.f);
    rmsnorm_kernel<<<TOK_, 256>>>(p_qa, q_ln, p_qa, QR_, QR_, QR_);
    mma_gemm<false,false,false><<<dim3((H_*QKD_)/GBN, TOK_/GBM, 1), 256, SMEM_NN>>>(
        p_qa, p_wqb, p_q, TOK_, H_*QKD_, QR_, QR_, H_*QKD_, H_*QKD_, 0, 0, 0, 1.f);

    // kv path
    mma_gemm<false,false,false><<<dim3((KVR_+ROPE_+GBN-1)/GBN, TOK_/GBM, 1), 256, SMEM_NN>>>(
        p_hsc, p_wkva, p_kvc, TOK_, KVR_+ROPE_, IN_, IN_, KVR_+ROPE_, KVR_+ROPE_, 0, 0, 0, 1.f);
    rmsnorm_kernel<<<TOK_, 256>>>(p_kvc, kv_ln, p_kvn, KVR_, KVR_+ROPE_, KVR_);
    mma_gemm<false,false,false><<<dim3((H_*(NOPE_+VHD_))/GBN, TOK_/GBM, 1), 256, SMEM_NN>>>(
        p_kvn, p_wkvb, p_kv, TOK_, H_*(NOPE_+VHD_), KVR_, KVR_,
        H_*(NOPE_+VHD_), H_*(NOPE_+VHD_), 0, 0, 0, 1.f);

    // RoPE table + assemble Q/K/V (tf32-rounded at store)
    build_cs<<<(TOK_*32 + 255)/256, 256>>>(pos);
    int nq = BH_ * S_ * QKD_;
    build_q<<<(nq + 255) / 256, 256>>>();
    build_k<<<(nq + 255) / 256, 256>>>();
    int nv = BH_ * S_ * VHD_;
    build_v<<<(nv + 255) / 256, 256>>>();

    // scores = scale * Qf @ Kf^T (batched, causal block-skip); fp32 out
    float scale = 1.f / sqrtf((float)QKD_);
    mma_gemm<true,true,false><<<dim3(S_/GBN, S_/GBM, BH_), 256, SMEM_TB>>>(
        p_Qf, p_Kf, p_Sc, S_, S_, QKD_, QKD_, QKD_, S_,
        (size_t)S_*QKD_, (size_t)S_*QKD_, (size_t)S_*S_, scale);

    softmax_causal<<<BH_ * S_, 256>>>();

    // PV: ctx = attn @ V (batched, causal K-limit, tf32-rounded out)
    mma_gemm<false,false,true><<<dim3(1, S_/GBM, BH_), 256, SMEM_NN>>>(
        p_Sc, p_Vf, p_ctx, S_, VHD_, S_, S_, VHD_, H_*VHD_,
        (size_t)S_*S_, (size_t)S_*VHD_, 0, 1.f);

    // output projection (fp32 out to harness buffer)
    mma_gemm<false,false,false><<<dim3(HID_/GBN, TOK_/GBM, 1), 256, SMEM_NN>>>(
        p_ctx, p_wo, out, TOK_, HID_, HID_, HID_, HID_, HID_, 0, 0, 0, 1.f);
}

// round 7
// speedup vs baseline: 1.5815x; 1.5815x over previous
#include <cuda_runtime.h>
#include <cuda_fp16.h>
#include <math.h>
#include <stdint.h>

// ---------------- problem constants ----------------
#define B_    2
#define S_    2048
#define HID_  2048
#define IN_   4096
#define H_    16
#define NOPE_ 128
#define ROPE_ 64
#define VHD_  128
#define QKD_  192
#define QR_   1536
#define KVR_  512
#define TOK_  (B_*S_)
#define BH_   (B_*H_)
#define EPS_  1e-6f
#define KVO_  (KVR_+ROPE_)   // 576
#define KVAP_ 640            // padded to 128-multiple

// ---------------- scratch ----------------
__device__ float  g_qa  [TOK_*QR_];                // dense out fp32
__device__ __half g_qah [TOK_*QR_];                // rms(qa) half
__device__ float  g_q   [TOK_*(H_*QKD_)];          // q proj fp32
__device__ float  g_kvc [TOK_*KVO_];               // kv_a out fp32
__device__ __half g_kvnh[TOK_*KVR_];               // rms(kv) half
__device__ float  g_kv  [TOK_*(H_*(NOPE_+VHD_))];  // kv_b out fp32
__device__ __half g_Qfh [BH_*S_*QKD_];
__device__ __half g_Kfh [BH_*S_*QKD_];
__device__ __half g_Vth [BH_*VHD_*S_];             // V transposed [bh][d][s]
__device__ float  g_Sc  [(size_t)BH_*S_*S_];       // scores fp32
__device__ __half g_Sch [(size_t)BH_*S_*S_];       // exp probs half (unnormalized)
__device__ float  g_tot [BH_*S_];                  // 1/rowsum
__device__ __half g_ctxh[TOK_*(H_*VHD_)];
__device__ float  g_cos [TOK_*32];
__device__ float  g_sin [TOK_*32];
// half copies of inputs (weights transposed to [N,K])
__device__ __half g_hsch [TOK_*IN_];
__device__ __half g_wqah [QR_*IN_];
__device__ __half g_wqbh [(H_*QKD_)*QR_];
__device__ __half g_wkvah[KVAP_*IN_];
__device__ __half g_wkvbh[(H_*(NOPE_+VHD_))*KVR_];
__device__ __half g_woh  [HID_*HID_];

// ---------------- helpers ----------------
__device__ __forceinline__ void mma_f16(float c[4], const uint32_t a[4], const uint32_t b[2]) {
    asm volatile(
        "mma.sync.aligned.m16n8k16.row.col.f32.f16.f16.f32 "
        "{%0,%1,%2,%3}, {%4,%5,%6,%7}, {%8,%9}, {%0,%1,%2,%3};"
        : "+f"(c[0]), "+f"(c[1]), "+f"(c[2]), "+f"(c[3])
        : "r"(a[0]), "r"(a[1]), "r"(a[2]), "r"(a[3]), "r"(b[0]), "r"(b[1]));
}
__device__ __forceinline__ void cp16(uint32_t dst, const void* src) {
    asm volatile("cp.async.cg.shared.global [%0], [%1], 16;\n" :: "r"(dst), "l"(src));
}
__device__ __forceinline__ void cp_commit() {
    asm volatile("cp.async.commit_group;\n" ::: "memory");
}

// ---------------- unified fp16 TB GEMM ----------------
// C[M,N] = alpha * A[M,K] @ B[N,K]^T, fp32 accum.
// 128x128 CTA tile, BK=32 halves, 4-stage cp.async, 8 warps of 64x32.
#define HBK 32
#define HP  40                       // padded pitch (halves)
#define H_STG (128*HP)               // halves per stage per matrix
#define HSTG  4
#define SMEM_H (HSTG * 2 * H_STG * 2)  // 81920 bytes

template<bool CAUSAL, bool PV>
__global__ __launch_bounds__(256, 2) void hgemm(
    const __half* __restrict__ A, const __half* __restrict__ B,
    float* __restrict__ Cf, __half* __restrict__ Ch,
    int M, int N, int K, int lda, int ldb, int ldc,
    size_t sA, size_t sB, size_t sC, float alpha,
    const float* __restrict__ invtot)
{
    if (CAUSAL && blockIdx.x > blockIdx.y) return;

    extern __shared__ __half hsm[];
    __half* Asm = hsm;
    __half* Bsm = hsm + HSTG * H_STG;
    const uint32_t sA32 = (uint32_t)__cvta_generic_to_shared(Asm);
    const uint32_t sB32 = (uint32_t)__cvta_generic_to_shared(Bsm);

    const int bz = blockIdx.z;
    A += (size_t)bz * sA;
    B += (size_t)bz * sB;
    size_t cOff;
    if (PV) cOff = (size_t)(bz / H_) * S_ * ldc + (size_t)(bz % H_) * VHD_;
    else    cOff = (size_t)bz * sC;

    const int Keff = PV ? min(K, (int)(blockIdx.y + 1) * 128) : K;
    const int nt = Keff / HBK;

    const int tid  = threadIdx.x;
    const int lane = tid & 31;
    const int g    = lane >> 2;
    const int tig  = lane & 3;
    const int wid  = tid >> 5;
    const int wm   = wid & 1;
    const int wn   = wid >> 1;
    const int rowBase = blockIdx.y * 128;
    const int colBase = blockIdx.x * 128;

    // loaders: thread -> row r=tid>>1, half-offset (tid&1)*16, two 16B chunks
    const int r  = tid >> 1;
    const int co = (tid & 1) << 4;
    const __half* Ap = A + (size_t)(rowBase + r) * lda + co;
    const __half* Bp = B + (size_t)(colBase + r) * ldb + co;
    const uint32_t a_dst = sA32 + (uint32_t)(r * HP + co) * 2u;
    const uint32_t b_dst = sB32 + (uint32_t)(r * HP + co) * 2u;

    auto load_stage = [&](int st, int kc) {
        const uint32_t so = (uint32_t)(st * H_STG) * 2u;
        const __half* as = Ap + kc * HBK;
        const __half* bs = Bp + kc * HBK;
        cp16(a_dst + so,      as);
        cp16(a_dst + so + 16, as + 8);
        cp16(b_dst + so,      bs);
        cp16(b_dst + so + 16, bs + 8);
        cp_commit();
    };

    float acc[4][4][4];
    #pragma unroll
    for (int i = 0; i < 4; i++)
        #pragma unroll
        for (int j = 0; j < 4; j++)
            #pragma unroll
            for (int q = 0; q < 4; q++) acc[i][j][q] = 0.f;

    #pragma unroll
    for (int s = 0; s < HSTG - 1; s++) {
        if (s < nt) load_stage(s, s);
        else        cp_commit();
    }

    for (int t = 0; t < nt; t++) {
        asm volatile("cp.async.wait_group 2;\n" ::: "memory");
        __syncthreads();

        const int tn = t + HSTG - 1;
        if (tn < nt) load_stage(tn % HSTG, tn);
        else         cp_commit();

        const __half* Ab = Asm + (t % HSTG) * H_STG;
        const __half* Bb = Bsm + (t % HSTG) * H_STG;

        #pragma unroll
        for (int ks = 0; ks < 2; ks++) {
            const int kb = ks * 16;
            uint32_t afr[4][4], bfr[4][2];
            #pragma unroll
            for (int fm = 0; fm < 4; fm++) {
                const int m = wm * 64 + fm * 16 + g;
                afr[fm][0] = *(const uint32_t*)(Ab + (size_t)m       * HP + kb + 2*tig);
                afr[fm][1] = *(const uint32_t*)(Ab + (size_t)(m + 8) * HP + kb + 2*tig);
                afr[fm][2] = *(const uint32_t*)(Ab + (size_t)m       * HP + kb + 2*tig + 8);
                afr[fm][3] = *(const uint32_t*)(Ab + (size_t)(m + 8) * HP + kb + 2*tig + 8);
            }
            #pragma unroll
            for (int fn = 0; fn < 4; fn++) {
                const int n = wn * 32 + fn * 8 + g;
                bfr[fn][0] = *(const uint32_t*)(Bb + (size_t)n * HP + kb + 2*tig);
                bfr[fn][1] = *(const uint32_t*)(Bb + (size_t)n * HP + kb + 2*tig + 8);
            }
            #pragma unroll
            for (int fm = 0; fm < 4; fm++)
                #pragma unroll
                for (int fn = 0; fn < 4; fn++)
                    mma_f16(acc[fm][fn], afr[fm], bfr[fn]);
        }
    }

    // epilogue
    #pragma unroll
    for (int fm = 0; fm < 4; fm++) {
        #pragma unroll
        for (int fn = 0; fn < 4; fn++) {
            const int row = rowBase + wm * 64 + fm * 16 + g;
            const int col = colBase + wn * 32 + fn * 8 + tig * 2;
            if (col < N) {
                float v0 = acc[fm][fn][0] * alpha, v1 = acc[fm][fn][1] * alpha;
                float v2 = acc[fm][fn][2] * alpha, v3 = acc[fm][fn][3] * alpha;
                if (PV) {
                    float it0 = invtot[(size_t)bz * S_ + row];
                    float it1 = invtot[(size_t)bz * S_ + row + 8];
                    *(__half2*)&Ch[cOff + (size_t)row * ldc + col] =
                        __floats2half2_rn(v0 * it0, v1 * it0);
                    *(__half2*)&Ch[cOff + (size_t)(row + 8) * ldc + col] =
                        __floats2half2_rn(v2 * it1, v3 * it1);
                } else {
                    *(float2*)&Cf[cOff + (size_t)row * ldc + col]       = make_float2(v0, v1);
                    *(float2*)&Cf[cOff + (size_t)(row + 8) * ldc + col] = make_float2(v2, v3);
                }
            }
        }
    }
}

// ---------------- converts ----------------
__global__ void cvt_h(const float* __restrict__ src, __half* __restrict__ dst, int n4) {
    int i = blockIdx.x * blockDim.x + threadIdx.x;
    if (i >= n4) return;
    float4 v = ((const float4*)src)[i];
    ((__half2*)dst)[2*i]   = __floats2half2_rn(v.x, v.y);
    ((__half2*)dst)[2*i+1] = __floats2half2_rn(v.z, v.w);
}

// src [K,N] row-major -> dst [Npad,K] half, zero-padded rows
__global__ void transpose_h(const float* __restrict__ src, __half* __restrict__ dst,
                            int K, int N, int Npad)
{
    __shared__ float tile[32][33];
    const int k0 = blockIdx.y * 32, n0 = blockIdx.x * 32;
    const int tx = threadIdx.x, ty = threadIdx.y;
    #pragma unroll
    for (int i = ty; i < 32; i += 8) {
        int k = k0 + i, n = n0 + tx;
        tile[i][tx] = (k < K && n < N) ? src[(size_t)k * N + n] : 0.f;
    }
    __syncthreads();
    #pragma unroll
    for (int i = ty; i < 32; i += 8) {
        int n = n0 + i, k = k0 + tx;
        if (n < Npad && k < K) dst[(size_t)n * K + k] = __float2half(tile[tx][i]);
    }
}

// ---------------- block reductions ----------------
__device__ __forceinline__ float block_reduce_max(float v, float* sbuf) {
    int tid = threadIdx.x;
    sbuf[tid] = v; __syncthreads();
    #pragma unroll
    for (int s = 128; s > 0; s >>= 1) {
        if (tid < s) sbuf[tid] = fmaxf(sbuf[tid], sbuf[tid + s]);
        __syncthreads();
    }
    float r = sbuf[0]; __syncthreads();
    return r;
}
__device__ __forceinline__ float block_reduce_sum(float v, float* sbuf) {
    int tid = threadIdx.x;
    sbuf[tid] = v; __syncthreads();
    #pragma unroll
    for (int s = 128; s > 0; s >>= 1) {
        if (tid < s) sbuf[tid] = sbuf[tid] + sbuf[tid + s];
        __syncthreads();
    }
    float r = sbuf[0]; __syncthreads();
    return r;
}

// ---------------- rmsnorm (fp32 in, half out) ----------------
__global__ __launch_bounds__(256) void rmsnorm_h(const float* __restrict__ x,
                                                 const float* __restrict__ w,
                                                 __half* __restrict__ y,
                                                 int n, int si, int so)
{
    __shared__ float sbuf[256];
    const size_t row = blockIdx.x;
    const float* xr = x + row * si;
    float acc = 0.f;
    for (int j = threadIdx.x; j < n; j += 256) { float v = xr[j]; acc += v * v; }
    float tot = block_reduce_sum(acc, sbuf);
    float scale = rsqrtf(tot / (float)n + EPS_);
    __half* yr = y + row * so;
    for (int j = threadIdx.x; j < n; j += 256) yr[j] = __float2half(xr[j] * scale * w[j]);
}

// ---------------- RoPE table + assembly ----------------
__global__ void build_cs(const int* __restrict__ pos) {
    int idx = blockIdx.x * blockDim.x + threadIdx.x;
    if (idx >= TOK_ * 32) return;
    int j = idx & 31, tok = idx >> 5;
    float inv = powf(10000.f, -((float)(2 * j)) / 64.f);
    float ang = (float)pos[tok] * inv;
    g_cos[idx] = cosf(ang);
    g_sin[idx] = sinf(ang);
}

__device__ __forceinline__ float rope_val(const float* pair_base, int drel, int tok) {
    int j = drel >> 1;
    float c = g_cos[tok * 32 + j], s = g_sin[tok * 32 + j];
    float ev = pair_base[2*j], ov = pair_base[2*j + 1];
    return ((drel & 1) == 0) ? (ev * c - ov * s) : (ov * c + ev * s);
}

__global__ void build_q() {
    int idx = blockIdx.x * blockDim.x + threadIdx.x;
    if (idx >= BH_ * S_ * QKD_) return;
    int d  = idx % QKD_;
    int r  = idx / QKD_;
    int s  = r % S_;
    int bh = r / S_;
    int b = bh / H_, h = bh % H_;
    int tok = b * S_ + s;
    const float* src = g_q + (size_t)tok * (H_*QKD_) + h * QKD_;
    float v;
    if (d < NOPE_) v = src[d];
    else           v = rope_val(src + NOPE_, d - NOPE_, tok);
    g_Qfh[idx] = __float2half(v);
}

__global__ void build_k() {
    int idx = blockIdx.x * blockDim.x + threadIdx.x;
    if (idx >= BH_ * S_ * QKD_) return;
    int d  = idx % QKD_;
    int r  = idx / QKD_;
    int s  = r % S_;
    int bh = r / S_;
    int b = bh / H_, h = bh % H_;
    int tok = b * S_ + s;
    float v;
    if (d < NOPE_) v = g_kv[(size_t)tok * (H_*(NOPE_+VHD_)) + h * (NOPE_+VHD_) + d];
    else           v = rope_val(g_kvc + (size_t)tok * KVO_ + KVR_, d - NOPE_, tok);
    g_Kfh[idx] = __float2half(v);
}

// V transposed: g_Vth[bh][d][s]
__global__ void build_vt() {
    int idx = blockIdx.x * blockDim.x + threadIdx.x;
    if (idx >= BH_ * VHD_ * S_) return;
    int s  = idx % S_;
    int r  = idx / S_;
    int d  = r % VHD_;
    int bh = r / VHD_;
    int b = bh / H_, h = bh % H_;
    int tok = b * S_ + s;
    g_Vth[idx] = __float2half(g_kv[(size_t)tok * (H_*(NOPE_+VHD_)) + h * (NOPE_+VHD_) + NOPE_ + d]);
}

// ---------------- causal softmax: write unnormalized exp (half) + 1/sum ----------------
__global__ __launch_bounds__(256) void softmax_causal() {
    __shared__ float sbuf[256];
    const int row = blockIdx.x;            // bh*S + q
    const int q = row % S_;
    const float* p = g_Sc + (size_t)row * S_;
    __half* ph = g_Sch + (size_t)row * S_;
    const int n = q + 1;

    float m = -INFINITY;
    for (int j = threadIdx.x; j < n; j += 256) m = fmaxf(m, p[j]);
    m = block_reduce_max(m, sbuf);

    float acc = 0.f;
    for (int j = threadIdx.x; j < n; j += 256) {
        __half eh = __float2half(expf(p[j] - m));
        ph[j] = eh;
        acc += __half2float(eh);
    }
    float tot = block_reduce_sum(acc, sbuf);
    if (threadIdx.x == 0) g_tot[row] = 1.f / tot;
    for (int j = n + threadIdx.x; j < S_; j += 256) ph[j] = __half(0.f);
}

// ---------------- launcher ----------------
extern "C" void kernel_launch(void* const* d_in, const int* in_sizes, int n_in,
                              void* d_out, int out_size)
{
    const float* hs    = (const float*)d_in[0];
    const float* Wq_a  = (const float*)d_in[1];
    const float* q_ln  = (const float*)d_in[2];
    const float* Wq_b  = (const float*)d_in[3];
    const float* Wkv_a = (const float*)d_in[4];
    const float* kv_ln = (const float*)d_in[5];
    const float* Wkv_b = (const float*)d_in[6];
    const float* Wo    = (const float*)d_in[7];
    const int*   pos   = (const int*)  d_in[8];
    float* out = (float*)d_out;

    float *p_qa, *p_q, *p_kvc, *p_kv, *p_Sc, *p_tot;
    __half *p_qah, *p_kvnh, *p_Qfh, *p_Kfh, *p_Vth, *p_Sch, *p_ctxh;
    __half *p_hsch, *p_wqah, *p_wqbh, *p_wkvah, *p_wkvbh, *p_woh;
    cudaGetSymbolAddress((void**)&p_qa,   g_qa);
    cudaGetSymbolAddress((void**)&p_qah,  g_qah);
    cudaGetSymbolAddress((void**)&p_q,    g_q);
    cudaGetSymbolAddress((void**)&p_kvc,  g_kvc);
    cudaGetSymbolAddress((void**)&p_kvnh, g_kvnh);
    cudaGetSymbolAddress((void**)&p_kv,   g_kv);
    cudaGetSymbolAddress((void**)&p_Qfh,  g_Qfh);
    cudaGetSymbolAddress((void**)&p_Kfh,  g_Kfh);
    cudaGetSymbolAddress((void**)&p_Vth,  g_Vth);
    cudaGetSymbolAddress((void**)&p_Sc,   g_Sc);
    cudaGetSymbolAddress((void**)&p_Sch,  g_Sch);
    cudaGetSymbolAddress((void**)&p_tot,  g_tot);
    cudaGetSymbolAddress((void**)&p_ctxh, g_ctxh);
    cudaGetSymbolAddress((void**)&p_hsch, g_hsch);
    cudaGetSymbolAddress((void**)&p_wqah, g_wqah);
    cudaGetSymbolAddress((void**)&p_wqbh, g_wqbh);
    cudaGetSymbolAddress((void**)&p_wkvah,g_wkvah);
    cudaGetSymbolAddress((void**)&p_wkvbh,g_wkvbh);
    cudaGetSymbolAddress((void**)&p_woh,  g_woh);

    static bool attr_done = false;
    if (!attr_done) {
        cudaFuncSetAttribute(hgemm<false,false>,
                             cudaFuncAttributeMaxDynamicSharedMemorySize, SMEM_H);
        cudaFuncSetAttribute(hgemm<true,false>,
                             cudaFuncAttributeMaxDynamicSharedMemorySize, SMEM_H);
        cudaFuncSetAttribute(hgemm<false,true>,
                             cudaFuncAttributeMaxDynamicSharedMemorySize, SMEM_H);
        attr_done = true;
    }

    // convert inputs to half (weights transposed to [N,K])
    cvt_h<<<(TOK_*IN_/4 + 255)/256, 256>>>(hs, p_hsch, TOK_*IN_/4);
    dim3 tb(32, 8);
    transpose_h<<<dim3(QR_/32, IN_/32), tb>>>(Wq_a, p_wqah, IN_, QR_, QR_);
    transpose_h<<<dim3((H_*QKD_)/32, QR_/32), tb>>>(Wq_b, p_wqbh, QR_, H_*QKD_, H_*QKD_);
    transpose_h<<<dim3(KVAP_/32, IN_/32), tb>>>(Wkv_a, p_wkvah, IN_, KVO_, KVAP_);
    transpose_h<<<dim3((H_*(NOPE_+VHD_))/32, KVR_/32), tb>>>(Wkv_b, p_wkvbh,
                                                             KVR_, H_*(NOPE_+VHD_), H_*(NOPE_+VHD_));
    transpose_h<<<dim3(HID_/32, HID_/32), tb>>>(Wo, p_woh, HID_, HID_, HID_);

    // q path
    hgemm<false,false><<<dim3(QR_/128, TOK_/128), 256, SMEM_H>>>(
        p_hsch, p_wqah, p_qa, nullptr, TOK_, QR_, IN_, IN_, IN_, QR_,
        0, 0, 0, 1.f, nullptr);
    rmsnorm_h<<<TOK_, 256>>>(p_qa, q_ln, p_qah, QR_, QR_, QR_);
    hgemm<false,false><<<dim3((H_*QKD_)/128, TOK_/128), 256, SMEM_H>>>(
        p_qah, p_wqbh, p_q, nullptr, TOK_, H_*QKD_, QR_, QR_, QR_, H_*QKD_,
        0, 0, 0, 1.f, nullptr);

    // kv path
    hgemm<false,false><<<dim3(KVAP_/128, TOK_/128), 256, SMEM_H>>>(
        p_hsch, p_wkvah, p_kvc, nullptr, TOK_, KVO_, IN_, IN_, IN_, KVO_,
        0, 0, 0, 1.f, nullptr);
    rmsnorm_h<<<TOK_, 256>>>(p_kvc, kv_ln, p_kvnh, KVR_, KVO_, KVR_);
    hgemm<false,false><<<dim3((H_*(NOPE_+VHD_))/128, TOK_/128), 256, SMEM_H>>>(
        p_kvnh, p_wkvbh, p_kv, nullptr, TOK_, H_*(NOPE_+VHD_), KVR_, KVR_, KVR_,
        H_*(NOPE_+VHD_), 0, 0, 0, 1.f, nullptr);

    // RoPE + assemble
    build_cs<<<(TOK_*32 + 255)/256, 256>>>(pos);
    int nq = BH_ * S_ * QKD_;
    build_q<<<(nq + 255) / 256, 256>>>();
    build_k<<<(nq + 255) / 256, 256>>>();
    int nv = BH_ * VHD_ * S_;
    build_vt<<<(nv + 255) / 256, 256>>>();

    // scores = scale * Qf @ Kf^T
    float scale = 1.f / sqrtf((float)QKD_);
    hgemm<true,false><<<dim3(S_/128, S_/128, BH_), 256, SMEM_H>>>(
        p_Qfh, p_Kfh, p_Sc, nullptr, S_, S_, QKD_, QKD_, QKD_, S_,
        (size_t)S_*QKD_, (size_t)S_*QKD_, (size_t)S_*S_, scale, nullptr);

    softmax_causal<<<BH_ * S_, 256>>>();

    // PV: ctx = (exp probs @ V^T^T) * invtot, half out
    hgemm<false,true><<<dim3(1, S_/128, BH_), 256, SMEM_H>>>(
        p_Sch, p_Vth, nullptr, p_ctxh, S_, VHD_, S_, S_, S_, H_*VHD_,
        (size_t)S_*S_, (size_t)VHD_*S_, 0, 1.f, p_tot);

    // output projection
    hgemm<false,false><<<dim3(HID_/128, TOK_/128), 256, SMEM_H>>>(
        p_ctxh, p_woh, out, nullptr, TOK_, HID_, HID_, HID_, HID_, HID_,
        0, 0, 0, 1.f, nullptr);
}

// round 9
// speedup vs baseline: 1.8136x; 1.1467x over previous
#include <cuda_runtime.h>
#include <cuda_fp16.h>
#include <math.h>
#include <stdint.h>

// ---------------- problem constants ----------------
#define B_    2
#define S_    2048
#define HID_  2048
#define IN_   4096
#define H_    16
#define NOPE_ 128
#define ROPE_ 64
#define VHD_  128
#define QKD_  192
#define QR_   1536
#define KVR_  512
#define TOK_  (B_*S_)
#define BH_   (B_*H_)
#define EPS_  1e-6f
#define KVO_  (KVR_+ROPE_)   // 576
#define KVAP_ 640

// ---------------- scratch ----------------
__device__ float  g_qa  [TOK_*QR_];
__device__ __half g_qah [TOK_*QR_];
__device__ float  g_q   [TOK_*(H_*QKD_)];
__device__ float  g_kvc [TOK_*KVO_];
__device__ __half g_kvnh[TOK_*KVR_];
__device__ float  g_kv  [TOK_*(H_*(NOPE_+VHD_))];
__device__ __half g_Qfh [BH_*S_*QKD_];
__device__ __half g_Kfh [BH_*S_*QKD_];
__device__ __half g_Vth [BH_*VHD_*S_];             // V^T [bh][d][s]
__device__ __half g_ctxh[TOK_*(H_*VHD_)];
__device__ float  g_cos [TOK_*32];
__device__ float  g_sin [TOK_*32];
__device__ __half g_hsch [TOK_*IN_];
__device__ __half g_wqah [QR_*IN_];
__device__ __half g_wqbh [(H_*QKD_)*QR_];
__device__ __half g_wkvah[KVAP_*IN_];
__device__ __half g_wkvbh[(H_*(NOPE_+VHD_))*KVR_];
__device__ __half g_woh  [HID_*HID_];

// ---------------- helpers ----------------
__device__ __forceinline__ void mma_f16(float c[4], const uint32_t a[4], const uint32_t b[2]) {
    asm volatile(
        "mma.sync.aligned.m16n8k16.row.col.f32.f16.f16.f32 "
        "{%0,%1,%2,%3}, {%4,%5,%6,%7}, {%8,%9}, {%0,%1,%2,%3};"
        : "+f"(c[0]), "+f"(c[1]), "+f"(c[2]), "+f"(c[3])
        : "r"(a[0]), "r"(a[1]), "r"(a[2]), "r"(a[3]), "r"(b[0]), "r"(b[1]));
}
__device__ __forceinline__ void cp16(uint32_t dst, const void* src) {
    asm volatile("cp.async.cg.shared.global [%0], [%1], 16;\n" :: "r"(dst), "l"(src));
}
__device__ __forceinline__ void cp_commit() {
    asm volatile("cp.async.commit_group;\n" ::: "memory");
}
__device__ __forceinline__ uint32_t h2u(__half2 h) { return *(uint32_t*)&h; }

// ---------------- dense fp16 TB GEMM (fp32 out) ----------------
#define HBK 32
#define HP  40
#define H_STG (128*HP)
#define HSTG  4
#define SMEM_H (HSTG * 2 * H_STG * 2)

__global__ __launch_bounds__(256, 2) void hgemm(
    const __half* __restrict__ A, const __half* __restrict__ B, float* __restrict__ C,
    int M, int N, int K, int lda, int ldb, int ldc)
{
    extern __shared__ __half hsm[];
    __half* Asm = hsm;
    __half* Bsm = hsm + HSTG * H_STG;
    const uint32_t sA32 = (uint32_t)__cvta_generic_to_shared(Asm);
    const uint32_t sB32 = (uint32_t)__cvta_generic_to_shared(Bsm);

    const int nt = K / HBK;
    const int tid  = threadIdx.x;
    const int lane = tid & 31;
    const int g    = lane >> 2;
    const int tig  = lane & 3;
    const int wid  = tid >> 5;
    const int wm   = wid & 1;
    const int wn   = wid >> 1;
    const int rowBase = blockIdx.y * 128;
    const int colBase = blockIdx.x * 128;

    const int r  = tid >> 1;
    const int co = (tid & 1) << 4;
    const __half* Ap = A + (size_t)(rowBase + r) * lda + co;
    const __half* Bp = B + (size_t)(colBase + r) * ldb + co;
    const uint32_t a_dst = sA32 + (uint32_t)(r * HP + co) * 2u;
    const uint32_t b_dst = sB32 + (uint32_t)(r * HP + co) * 2u;

    auto load_stage = [&](int st, int kc) {
        const uint32_t so = (uint32_t)(st * H_STG) * 2u;
        const __half* as = Ap + kc * HBK;
        const __half* bs = Bp + kc * HBK;
        cp16(a_dst + so,      as);
        cp16(a_dst + so + 16, as + 8);
        cp16(b_dst + so,      bs);
        cp16(b_dst + so + 16, bs + 8);
        cp_commit();
    };

    float acc[4][4][4];
    #pragma unroll
    for (int i = 0; i < 4; i++)
        #pragma unroll
        for (int j = 0; j < 4; j++)
            #pragma unroll
            for (int q = 0; q < 4; q++) acc[i][j][q] = 0.f;

    #pragma unroll
    for (int s = 0; s < HSTG - 1; s++) {
        if (s < nt) load_stage(s, s);
        else        cp_commit();
    }

    for (int t = 0; t < nt; t++) {
        asm volatile("cp.async.wait_group 2;\n" ::: "memory");
        __syncthreads();

        const int tn = t + HSTG - 1;
        if (tn < nt) load_stage(tn % HSTG, tn);
        else         cp_commit();

        const __half* Ab = Asm + (t % HSTG) * H_STG;
        const __half* Bb = Bsm + (t % HSTG) * H_STG;

        #pragma unroll
        for (int ks = 0; ks < 2; ks++) {
            const int kb = ks * 16;
            uint32_t afr[4][4], bfr[4][2];
            #pragma unroll
            for (int fm = 0; fm < 4; fm++) {
                const int m = wm * 64 + fm * 16 + g;
                afr[fm][0] = *(const uint32_t*)(Ab + (size_t)m       * HP + kb + 2*tig);
                afr[fm][1] = *(const uint32_t*)(Ab + (size_t)(m + 8) * HP + kb + 2*tig);
                afr[fm][2] = *(const uint32_t*)(Ab + (size_t)m       * HP + kb + 2*tig + 8);
                afr[fm][3] = *(const uint32_t*)(Ab + (size_t)(m + 8) * HP + kb + 2*tig + 8);
            }
            #pragma unroll
            for (int fn = 0; fn < 4; fn++) {
                const int n = wn * 32 + fn * 8 + g;
                bfr[fn][0] = *(const uint32_t*)(Bb + (size_t)n * HP + kb + 2*tig);
                bfr[fn][1] = *(const uint32_t*)(Bb + (size_t)n * HP + kb + 2*tig + 8);
            }
            #pragma unroll
            for (int fm = 0; fm < 4; fm++)
                #pragma unroll
                for (int fn = 0; fn < 4; fn++)
                    mma_f16(acc[fm][fn], afr[fm], bfr[fn]);
        }
    }

    #pragma unroll
    for (int fm = 0; fm < 4; fm++) {
        #pragma unroll
        for (int fn = 0; fn < 4; fn++) {
            const int row = rowBase + wm * 64 + fm * 16 + g;
            const int col = colBase + wn * 32 + fn * 8 + tig * 2;
            if (col < N) {
                *(float2*)&C[(size_t)row * ldc + col] =
                    make_float2(acc[fm][fn][0], acc[fm][fn][1]);
                *(float2*)&C[(size_t)(row + 8) * ldc + col] =
                    make_float2(acc[fm][fn][2], acc[fm][fn][3]);
            }
        }
    }
}

// ---------------- fused flash attention ----------------
// CTA: 128 q rows x one bh. 8 warps x 16 q rows. K/V tiles of 64, double-buffered.
#define FBQ 128
#define FBK 64
#define FQP 200                 // Q/K smem pitch (halves)
#define FVP 72                  // V smem pitch (halves)
#define FQ_SZ (FBQ*FQP)
#define FK_SZ (FBK*FQP)
#define FV_SZ (VHD_*FVP)
#define FSMEM ((FQ_SZ + 2*FK_SZ + 2*FV_SZ) * 2)

__global__ __launch_bounds__(256, 1) void flash_attn(float scale)
{
    extern __shared__ __half fsm[];
    __half* Qs  = fsm;
    __half* Ks0 = Qs + FQ_SZ;
    __half* Vs0 = Ks0 + 2 * FK_SZ;
    const uint32_t sQ = (uint32_t)__cvta_generic_to_shared(Qs);
    const uint32_t sK = (uint32_t)__cvta_generic_to_shared(Ks0);
    const uint32_t sV = (uint32_t)__cvta_generic_to_shared(Vs0);

    const int qt = (int)(gridDim.x - 1 - blockIdx.x);   // heavy tiles first
    const int bh = blockIdx.y;
    const int qbase = qt * FBQ;
    const int tid = threadIdx.x;
    const int wid = tid >> 5, lane = tid & 31, g = lane >> 2, tig = lane & 3;
    const int qr0 = wid * 16;

    const __half* Qg = g_Qfh + ((size_t)bh * S_ + qbase) * QKD_;
    const __half* Kg = g_Kfh + (size_t)bh * S_ * QKD_;
    const __half* Vg = g_Vth + (size_t)bh * VHD_ * S_;

    // one-time Q tile load: 2 threads/row, 96 halves (192B) each = 12 cp16
    {
        int r = tid >> 1, off = (tid & 1) * 96;
        const __half* src = Qg + (size_t)r * QKD_ + off;
        uint32_t dst = sQ + (uint32_t)(r * FQP + off) * 2u;
        #pragma unroll
        for (int c = 0; c < 12; c++) cp16(dst + c * 16, src + c * 8);
    }
    auto loadKV = [&](int st, int kt) {
        const int kbase = kt * FBK;
        // K: 4 threads/row, 48 halves (96B) each = 6 cp16
        {   int r = tid >> 2, off = (tid & 3) * 48;
            const __half* src = Kg + (size_t)(kbase + r) * QKD_ + off;
            uint32_t dst = sK + (uint32_t)(st * FK_SZ + r * FQP + off) * 2u;
            #pragma unroll
            for (int c = 0; c < 6; c++) cp16(dst + c * 16, src + c * 8);
        }
        // V: 2 threads/row(d), 32 halves (64B) each = 4 cp16
        {   int r = tid >> 1, off = (tid & 1) * 32;
            const __half* src = Vg + (size_t)r * S_ + kbase + off;
            uint32_t dst = sV + (uint32_t)(st * FV_SZ + r * FVP + off) * 2u;
            #pragma unroll
            for (int c = 0; c < 4; c++) cp16(dst + c * 16, src + c * 8);
        }
        cp_commit();
    };

    const int ktmax = (qbase + FBQ - 1) / FBK;
    loadKV(0, 0);   // commits Q loads too (same group)

    float oacc[16][4];
    #pragma unroll
    for (int i = 0; i < 16; i++)
        #pragma unroll
        for (int j = 0; j < 4; j++) oacc[i][j] = 0.f;
    float sm0 = -1e30f, sm1 = -1e30f, l0 = 0.f, l1 = 0.f;

    const int row0 = qbase + qr0 + g;
    const int row1 = row0 + 8;

    for (int kt = 0; kt <= ktmax; kt++) {
        const int st = kt & 1;
        if (kt < ktmax) {
            loadKV(st ^ 1, kt + 1);
            asm volatile("cp.async.wait_group 1;\n" ::: "memory");
        } else {
            asm volatile("cp.async.wait_group 0;\n" ::: "memory");
        }
        __syncthreads();

        const int kbase = kt * FBK;
        // warp-level skip of fully-masked tiles (all rows of this warp < kbase)
        if (kbase <= qbase + qr0 + 15) {
            const __half* Kb = Ks0 + st * FK_SZ;
            const __half* Vb = Vs0 + st * FV_SZ;

            // scores: 16 x 64
            float sacc[8][4];
            #pragma unroll
            for (int nb = 0; nb < 8; nb++)
                #pragma unroll
                for (int j = 0; j < 4; j++) sacc[nb][j] = 0.f;

            #pragma unroll
            for (int kc = 0; kc < 12; kc++) {
                const int kb = kc * 16;
                uint32_t a[4];
                a[0] = *(const uint32_t*)(Qs + (size_t)(qr0 + g)     * FQP + kb + 2*tig);
                a[1] = *(const uint32_t*)(Qs + (size_t)(qr0 + g + 8) * FQP + kb + 2*tig);
                a[2] = *(const uint32_t*)(Qs + (size_t)(qr0 + g)     * FQP + kb + 2*tig + 8);
                a[3] = *(const uint32_t*)(Qs + (size_t)(qr0 + g + 8) * FQP + kb + 2*tig + 8);
                #pragma unroll
                for (int nb = 0; nb < 8; nb++) {
                    const int n = nb * 8 + g;
                    uint32_t b[2];
                    b[0] = *(const uint32_t*)(Kb + (size_t)n * FQP + kb + 2*tig);
                    b[1] = *(const uint32_t*)(Kb + (size_t)n * FQP + kb + 2*tig + 8);
                    mma_f16(sacc[nb], a, b);
                }
            }

            // scale + causal mask (tiles straddling the diagonal)
            const bool need_mask = (kbase + FBK - 1) > (qbase + qr0);
            #pragma unroll
            for (int nb = 0; nb < 8; nb++) {
                const int c0 = kbase + nb * 8 + 2 * tig, c1 = c0 + 1;
                sacc[nb][0] *= scale; sacc[nb][1] *= scale;
                sacc[nb][2] *= scale; sacc[nb][3] *= scale;
                if (need_mask) {
                    if (c0 > row0) sacc[nb][0] = -1e30f;
                    if (c1 > row0) sacc[nb][1] = -1e30f;
                    if (c0 > row1) sacc[nb][2] = -1e30f;
                    if (c1 > row1) sacc[nb][3] = -1e30f;
                }
            }

            // online softmax
            float mx0 = -1e30f, mx1 = -1e30f;
            #pragma unroll
            for (int nb = 0; nb < 8; nb++) {
                mx0 = fmaxf(mx0, fmaxf(sacc[nb][0], sacc[nb][1]));
                mx1 = fmaxf(mx1, fmaxf(sacc[nb][2], sacc[nb][3]));
            }
            mx0 = fmaxf(mx0, __shfl_xor_sync(0xFFFFFFFFu, mx0, 1));
            mx0 = fmaxf(mx0, __shfl_xor_sync(0xFFFFFFFFu, mx0, 2));
            mx1 = fmaxf(mx1, __shfl_xor_sync(0xFFFFFFFFu, mx1, 1));
            mx1 = fmaxf(mx1, __shfl_xor_sync(0xFFFFFFFFu, mx1, 2));

            const float mn0 = fmaxf(sm0, mx0), mn1 = fmaxf(sm1, mx1);
            const float al0 = __expf(sm0 - mn0), al1 = __expf(sm1 - mn1);
            sm0 = mn0; sm1 = mn1;

            uint32_t pA[8], pB[8];
            float ps0 = 0.f, ps1 = 0.f;
            #pragma unroll
            for (int nb = 0; nb < 8; nb++) {
                const float e0 = __expf(sacc[nb][0] - mn0);
                const float e1 = __expf(sacc[nb][1] - mn0);
                const float e2 = __expf(sacc[nb][2] - mn1);
                const float e3 = __expf(sacc[nb][3] - mn1);
                ps0 += e0 + e1; ps1 += e2 + e3;
                pA[nb] = h2u(__floats2half2_rn(e0, e1));
                pB[nb] = h2u(__floats2half2_rn(e2, e3));
            }
            l0 = l0 * al0 + ps0;
            l1 = l1 * al1 + ps1;

            #pragma unroll
            for (int nb2 = 0; nb2 < 16; nb2++) {
                oacc[nb2][0] *= al0; oacc[nb2][1] *= al0;
                oacc[nb2][2] *= al1; oacc[nb2][3] *= al1;
            }

            // PV: P(16x64) @ V(64x128); A frags straight from score regs
            #pragma unroll
            for (int kc = 0; kc < 4; kc++) {
                uint32_t a[4] = { pA[2*kc], pB[2*kc], pA[2*kc+1], pB[2*kc+1] };
                #pragma unroll
                for (int nb2 = 0; nb2 < 16; nb2++) {
                    const int n = nb2 * 8 + g;
                    uint32_t b[2];
                    b[0] = *(const uint32_t*)(Vb + (size_t)n * FVP + kc * 16 + 2*tig);
                    b[1] = *(const uint32_t*)(Vb + (size_t)n * FVP + kc * 16 + 2*tig + 8);
                    mma_f16(oacc[nb2], a, b);
                }
            }
        }
        __syncthreads();
    }

    // finalize
    l0 += __shfl_xor_sync(0xFFFFFFFFu, l0, 1);
    l0 += __shfl_xor_sync(0xFFFFFFFFu, l0, 2);
    l1 += __shfl_xor_sync(0xFFFFFFFFu, l1, 1);
    l1 += __shfl_xor_sync(0xFFFFFFFFu, l1, 2);
    const float inv0 = 1.f / l0, inv1 = 1.f / l1;

    const int b = bh / H_, h = bh % H_;
    __half* out0 = g_ctxh + (size_t)(b * S_ + row0) * (H_*VHD_) + h * VHD_;
    __half* out1 = out0 + (size_t)8 * (H_*VHD_);
    #pragma unroll
    for (int nb2 = 0; nb2 < 16; nb2++) {
        const int d = nb2 * 8 + 2 * tig;
        *(__half2*)(out0 + d) = __floats2half2_rn(oacc[nb2][0] * inv0, oacc[nb2][1] * inv0);
        *(__half2*)(out1 + d) = __floats2half2_rn(oacc[nb2][2] * inv1, oacc[nb2][3] * inv1);
    }
}

// ---------------- converts ----------------
__global__ void cvt_h(const float* __restrict__ src, __half* __restrict__ dst, int n4) {
    int i = blockIdx.x * blockDim.x + threadIdx.x;
    if (i >= n4) return;
    float4 v = ((const float4*)src)[i];
    ((__half2*)dst)[2*i]   = __floats2half2_rn(v.x, v.y);
    ((__half2*)dst)[2*i+1] = __floats2half2_rn(v.z, v.w);
}

__global__ void transpose_h(const float* __restrict__ src, __half* __restrict__ dst,
                            int K, int N, int Npad)
{
    __shared__ float tile[32][33];
    const int k0 = blockIdx.y * 32, n0 = blockIdx.x * 32;
    const int tx = threadIdx.x, ty = threadIdx.y;
    #pragma unroll
    for (int i = ty; i < 32; i += 8) {
        int k = k0 + i, n = n0 + tx;
        tile[i][tx] = (k < K && n < N) ? src[(size_t)k * N + n] : 0.f;
    }
    __syncthreads();
    #pragma unroll
    for (int i = ty; i < 32; i += 8) {
        int n = n0 + i, k = k0 + tx;
        if (n < Npad && k < K) dst[(size_t)n * K + k] = __float2half(tile[tx][i]);
    }
}

// ---------------- reductions / rmsnorm ----------------
__device__ __forceinline__ float block_reduce_sum(float v, float* sbuf) {
    int tid = threadIdx.x;
    sbuf[tid] = v; __syncthreads();
    #pragma unroll
    for (int s = 128; s > 0; s >>= 1) {
        if (tid < s) sbuf[tid] = sbuf[tid] + sbuf[tid + s];
        __syncthreads();
    }
    float r = sbuf[0]; __syncthreads();
    return r;
}

__global__ __launch_bounds__(256) void rmsnorm_h(const float* __restrict__ x,
                                                 const float* __restrict__ w,
                                                 __half* __restrict__ y,
                                                 int n, int si, int so)
{
    __shared__ float sbuf[256];
    const size_t row = blockIdx.x;
    const float* xr = x + row * si;
    float acc = 0.f;
    for (int j = threadIdx.x; j < n; j += 256) { float v = xr[j]; acc += v * v; }
    float tot = block_reduce_sum(acc, sbuf);
    float scale = rsqrtf(tot / (float)n + EPS_);
    __half* yr = y + row * so;
    for (int j = threadIdx.x; j < n; j += 256) yr[j] = __float2half(xr[j] * scale * w[j]);
}

// ---------------- RoPE + assembly ----------------
__global__ void build_cs(const int* __restrict__ pos) {
    int idx = blockIdx.x * blockDim.x + threadIdx.x;
    if (idx >= TOK_ * 32) return;
    int j = idx & 31, tok = idx >> 5;
    float inv = powf(10000.f, -((float)(2 * j)) / 64.f);
    float ang = (float)pos[tok] * inv;
    g_cos[idx] = cosf(ang);
    g_sin[idx] = sinf(ang);
}

__device__ __forceinline__ float rope_val(const float* pair_base, int drel, int tok) {
    int j = drel >> 1;
    float c = g_cos[tok * 32 + j], s = g_sin[tok * 32 + j];
    float ev = pair_base[2*j], ov = pair_base[2*j + 1];
    return ((drel & 1) == 0) ? (ev * c - ov * s) : (ov * c + ev * s);
}

__global__ void build_q() {
    int idx = blockIdx.x * blockDim.x + threadIdx.x;
    if (idx >= BH_ * S_ * QKD_) return;
    int d  = idx % QKD_;
    int r  = idx / QKD_;
    int s  = r % S_;
    int bh = r / S_;
    int b = bh / H_, h = bh % H_;
    int tok = b * S_ + s;
    const float* src = g_q + (size_t)tok * (H_*QKD_) + h * QKD_;
    float v;
    if (d < NOPE_) v = src[d];
    else           v = rope_val(src + NOPE_, d - NOPE_, tok);
    g_Qfh[idx] = __float2half(v);
}

__global__ void build_k() {
    int idx = blockIdx.x * blockDim.x + threadIdx.x;
    if (idx >= BH_ * S_ * QKD_) return;
    int d  = idx % QKD_;
    int r  = idx / QKD_;
    int s  = r % S_;
    int bh = r / S_;
    int b = bh / H_, h = bh % H_;
    int tok = b * S_ + s;
    float v;
    if (d < NOPE_) v = g_kv[(size_t)tok * (H_*(NOPE_+VHD_)) + h * (NOPE_+VHD_) + d];
    else           v = rope_val(g_kvc + (size_t)tok * KVO_ + KVR_, d - NOPE_, tok);
    g_Kfh[idx] = __float2half(v);
}

__global__ void build_vt() {
    int idx = blockIdx.x * blockDim.x + threadIdx.x;
    if (idx >= BH_ * VHD_ * S_) return;
    int s  = idx % S_;
    int r  = idx / S_;
    int d  = r % VHD_;
    int bh = r / VHD_;
    int b = bh / H_, h = bh % H_;
    int tok = b * S_ + s;
    g_Vth[idx] = __float2half(g_kv[(size_t)tok * (H_*(NOPE_+VHD_)) + h * (NOPE_+VHD_) + NOPE_ + d]);
}

// ---------------- launcher ----------------
extern "C" void kernel_launch(void* const* d_in, const int* in_sizes, int n_in,
                              void* d_out, int out_size)
{
    const float* hs    = (const float*)d_in[0];
    const float* Wq_a  = (const float*)d_in[1];
    const float* q_ln  = (const float*)d_in[2];
    const float* Wq_b  = (const float*)d_in[3];
    const float* Wkv_a = (const float*)d_in[4];
    const float* kv_ln = (const float*)d_in[5];
    const float* Wkv_b = (const float*)d_in[6];
    const float* Wo    = (const float*)d_in[7];
    const int*   pos   = (const int*)  d_in[8];
    float* out = (float*)d_out;

    float *p_qa, *p_q, *p_kvc, *p_kv;
    __half *p_qah, *p_kvnh, *p_Qfh, *p_Kfh, *p_Vth, *p_ctxh;
    __half *p_hsch, *p_wqah, *p_wqbh, *p_wkvah, *p_wkvbh, *p_woh;
    cudaGetSymbolAddress((void**)&p_qa,   g_qa);
    cudaGetSymbolAddress((void**)&p_qah,  g_qah);
    cudaGetSymbolAddress((void**)&p_q,    g_q);
    cudaGetSymbolAddress((void**)&p_kvc,  g_kvc);
    cudaGetSymbolAddress((void**)&p_kvnh, g_kvnh);
    cudaGetSymbolAddress((void**)&p_kv,   g_kv);
    cudaGetSymbolAddress((void**)&p_Qfh,  g_Qfh);
    cudaGetSymbolAddress((void**)&p_Kfh,  g_Kfh);
    cudaGetSymbolAddress((void**)&p_Vth,  g_Vth);
    cudaGetSymbolAddress((void**)&p_ctxh, g_ctxh);
    cudaGetSymbolAddress((void**)&p_hsch, g_hsch);
    cudaGetSymbolAddress((void**)&p_wqah, g_wqah);
    cudaGetSymbolAddress((void**)&p_wqbh, g_wqbh);
    cudaGetSymbolAddress((void**)&p_wkvah,g_wkvah);
    cudaGetSymbolAddress((void**)&p_wkvbh,g_wkvbh);
    cudaGetSymbolAddress((void**)&p_woh,  g_woh);

    static bool attr_done = false;
    if (!attr_done) {
        cudaFuncSetAttribute(hgemm, cudaFuncAttributeMaxDynamicSharedMemorySize, SMEM_H);
        cudaFuncSetAttribute(flash_attn, cudaFuncAttributeMaxDynamicSharedMemorySize, FSMEM);
        attr_done = true;
    }

    // convert inputs (weights transposed to [N,K])
    cvt_h<<<(TOK_*IN_/4 + 255)/256, 256>>>(hs, p_hsch, TOK_*IN_/4);
    dim3 tb(32, 8);
    transpose_h<<<dim3(QR_/32, IN_/32), tb>>>(Wq_a, p_wqah, IN_, QR_, QR_);
    transpose_h<<<dim3((H_*QKD_)/32, QR_/32), tb>>>(Wq_b, p_wqbh, QR_, H_*QKD_, H_*QKD_);
    transpose_h<<<dim3(KVAP_/32, IN_/32), tb>>>(Wkv_a, p_wkvah, IN_, KVO_, KVAP_);
    transpose_h<<<dim3((H_*(NOPE_+VHD_))/32, KVR_/32), tb>>>(Wkv_b, p_wkvbh,
                                                             KVR_, H_*(NOPE_+VHD_), H_*(NOPE_+VHD_));
    transpose_h<<<dim3(HID_/32, HID_/32), tb>>>(Wo, p_woh, HID_, HID_, HID_);

    // q path
    hgemm<<<dim3(QR_/128, TOK_/128), 256, SMEM_H>>>(
        p_hsch, p_wqah, p_qa, TOK_, QR_, IN_, IN_, IN_, QR_);
    rmsnorm_h<<<TOK_, 256>>>(p_qa, q_ln, p_qah, QR_, QR_, QR_);
    hgemm<<<dim3((H_*QKD_)/128, TOK_/128), 256, SMEM_H>>>(
        p_qah, p_wqbh, p_q, TOK_, H_*QKD_, QR_, QR_, QR_, H_*QKD_);

    // kv path
    hgemm<<<dim3(KVAP_/128, TOK_/128), 256, SMEM_H>>>(
        p_hsch, p_wkvah, p_kvc, TOK_, KVO_, IN_, IN_, IN_, KVO_);
    rmsnorm_h<<<TOK_, 256>>>(p_kvc, kv_ln, p_kvnh, KVR_, KVO_, KVR_);
    hgemm<<<dim3((H_*(NOPE_+VHD_))/128, TOK_/128), 256, SMEM_H>>>(
        p_kvnh, p_wkvbh, p_kv, TOK_, H_*(NOPE_+VHD_), KVR_, KVR_, KVR_, H_*(NOPE_+VHD_));

    // RoPE + assemble
    build_cs<<<(TOK_*32 + 255)/256, 256>>>(pos);
    int nq = BH_ * S_ * QKD_;
    build_q<<<(nq + 255) / 256, 256>>>();
    build_k<<<(nq + 255) / 256, 256>>>();
    int nv = BH_ * VHD_ * S_;
    build_vt<<<(nv + 255) / 256, 256>>>();

    // fused attention
    float scale = 1.f / sqrtf((float)QKD_);
    flash_attn<<<dim3(S_/FBQ, BH_), 256, FSMEM>>>(scale);

    // output projection
    hgemm<<<dim3(HID_/128, TOK_/128), 256, SMEM_H>>>(
        p_ctxh, p_woh, out, TOK_, HID_, HID_, HID_, HID_, HID_);
}

// round 10
// speedup vs baseline: 2.0065x; 1.1064x over previous
#include <cuda_runtime.h>
#include <cuda_fp16.h>
#include <math.h>
#include <stdint.h>

// ---------------- problem constants ----------------
#define B_    2
#define S_    2048
#define HID_  2048
#define IN_   4096
#define H_    16
#define NOPE_ 128
#define ROPE_ 64
#define VHD_  128
#define QKD_  192
#define QR_   1536
#define KVR_  512
#define TOK_  (B_*S_)
#define BH_   (B_*H_)
#define EPS_  1e-6f
#define KVO_  (KVR_+ROPE_)   // 576
#define KVAP_ 640

// ---------------- scratch ----------------
__device__ float  g_qa  [TOK_*QR_];
__device__ __half g_qah [TOK_*QR_];
__device__ float  g_q   [TOK_*(H_*QKD_)];
__device__ float  g_kvc [TOK_*KVO_];
__device__ __half g_kvnh[TOK_*KVR_];
__device__ float  g_kv  [TOK_*(H_*(NOPE_+VHD_))];
__device__ __half g_Qfh [BH_*S_*QKD_];
__device__ __half g_Kfh [BH_*S_*QKD_];
__device__ __half g_Vth [BH_*VHD_*S_];             // V^T [bh][d][s]
__device__ __half g_ctxh[TOK_*(H_*VHD_)];
__device__ float  g_cos [TOK_*32];
__device__ float  g_sin [TOK_*32];
__device__ __half g_hsch [TOK_*IN_];
__device__ __half g_wqah [QR_*IN_];
__device__ __half g_wqbh [(H_*QKD_)*QR_];
__device__ __half g_wkvah[KVAP_*IN_];
__device__ __half g_wkvbh[(H_*(NOPE_+VHD_))*KVR_];
__device__ __half g_woh  [HID_*HID_];

// ---------------- helpers ----------------
__device__ __forceinline__ void mma_f16(float c[4], const uint32_t a[4], const uint32_t b[2]) {
    asm volatile(
        "mma.sync.aligned.m16n8k16.row.col.f32.f16.f16.f32 "
        "{%0,%1,%2,%3}, {%4,%5,%6,%7}, {%8,%9}, {%0,%1,%2,%3};"
        : "+f"(c[0]), "+f"(c[1]), "+f"(c[2]), "+f"(c[3])
        : "r"(a[0]), "r"(a[1]), "r"(a[2]), "r"(a[3]), "r"(b[0]), "r"(b[1]));
}
__device__ __forceinline__ void ldsm_x4(uint32_t& r0, uint32_t& r1, uint32_t& r2, uint32_t& r3,
                                        uint32_t addr) {
    asm volatile("ldmatrix.sync.aligned.m8n8.x4.shared.b16 {%0,%1,%2,%3}, [%4];"
                 : "=r"(r0), "=r"(r1), "=r"(r2), "=r"(r3) : "r"(addr));
}
__device__ __forceinline__ void cp16(uint32_t dst, const void* src) {
    asm volatile("cp.async.cg.shared.global [%0], [%1], 16;\n" :: "r"(dst), "l"(src));
}
__device__ __forceinline__ void cp_commit() {
    asm volatile("cp.async.commit_group;\n" ::: "memory");
}
__device__ __forceinline__ uint32_t h2u(__half2 h) { return *(uint32_t*)&h; }

// ---------------- dense fp16 TB GEMM (fp32 out), ldmatrix mainloop ----------------
#define HBK 32
#define HP  40
#define H_STG (128*HP)
#define HSTG  4
#define SMEM_H (HSTG * 2 * H_STG * 2)

__global__ __launch_bounds__(256, 2) void hgemm(
    const __half* __restrict__ A, const __half* __restrict__ B, float* __restrict__ C,
    int M, int N, int K, int lda, int ldb, int ldc)
{
    extern __shared__ __half hsm[];
    __half* Asm = hsm;
    __half* Bsm = hsm + HSTG * H_STG;
    const uint32_t sA32 = (uint32_t)__cvta_generic_to_shared(Asm);
    const uint32_t sB32 = (uint32_t)__cvta_generic_to_shared(Bsm);

    const int nt = K / HBK;
    const int tid  = threadIdx.x;
    const int lane = tid & 31;
    const int g    = lane >> 2;
    const int tig  = lane & 3;
    const int wid  = tid >> 5;
    const int wm   = wid & 1;
    const int wn   = wid >> 1;
    const int rowBase = blockIdx.y * 128;
    const int colBase = blockIdx.x * 128;

    const int r  = tid >> 1;
    const int co = (tid & 1) << 4;
    const __half* Ap = A + (size_t)(rowBase + r) * lda + co;
    const __half* Bp = B + (size_t)(colBase + r) * ldb + co;
    const uint32_t a_dst = sA32 + (uint32_t)(r * HP + co) * 2u;
    const uint32_t b_dst = sB32 + (uint32_t)(r * HP + co) * 2u;

    auto load_stage = [&](int st, int kc) {
        const uint32_t so = (uint32_t)(st * H_STG) * 2u;
        const __half* as = Ap + kc * HBK;
        const __half* bs = Bp + kc * HBK;
        cp16(a_dst + so,      as);
        cp16(a_dst + so + 16, as + 8);
        cp16(b_dst + so,      bs);
        cp16(b_dst + so + 16, bs + 8);
        cp_commit();
    };

    // ldmatrix lane-address bases (byte offsets within a stage)
    const uint32_t aLB = (uint32_t)(((wm * 64 + (lane & 15)) * HP + (lane >> 4) * 8) * 2);
    const uint32_t bLB = (uint32_t)(((wn * 32 + (lane & 7) + ((lane >> 4) & 1) * 8) * HP
                                     + ((lane >> 3) & 1) * 8) * 2);

    float acc[4][4][4];
    #pragma unroll
    for (int i = 0; i < 4; i++)
        #pragma unroll
        for (int j = 0; j < 4; j++)
            #pragma unroll
            for (int q = 0; q < 4; q++) acc[i][j][q] = 0.f;

    #pragma unroll
    for (int s = 0; s < HSTG - 1; s++) {
        if (s < nt) load_stage(s, s);
        else        cp_commit();
    }

    for (int t = 0; t < nt; t++) {
        asm volatile("cp.async.wait_group 2;\n" ::: "memory");
        __syncthreads();

        const int tn = t + HSTG - 1;
        if (tn < nt) load_stage(tn % HSTG, tn);
        else         cp_commit();

        const uint32_t stoff = (uint32_t)((t % HSTG) * H_STG) * 2u;
        const uint32_t aSt = sA32 + stoff + aLB;
        const uint32_t bSt = sB32 + stoff + bLB;

        #pragma unroll
        for (int ks = 0; ks < 2; ks++) {
            const uint32_t kby = (uint32_t)(ks * 32);   // 16 halves
            uint32_t afr[4][4], bfr[4][2];
            #pragma unroll
            for (int fm = 0; fm < 4; fm++)
                ldsm_x4(afr[fm][0], afr[fm][1], afr[fm][2], afr[fm][3],
                        aSt + (uint32_t)(fm * 16 * HP) * 2u + kby);
            #pragma unroll
            for (int fp = 0; fp < 2; fp++)
                ldsm_x4(bfr[2*fp][0], bfr[2*fp][1], bfr[2*fp+1][0], bfr[2*fp+1][1],
                        bSt + (uint32_t)(fp * 16 * HP) * 2u + kby);
            #pragma unroll
            for (int fm = 0; fm < 4; fm++)
                #pragma unroll
                for (int fn = 0; fn < 4; fn++)
                    mma_f16(acc[fm][fn], afr[fm], bfr[fn]);
        }
    }

    #pragma unroll
    for (int fm = 0; fm < 4; fm++) {
        #pragma unroll
        for (int fn = 0; fn < 4; fn++) {
            const int row = rowBase + wm * 64 + fm * 16 + g;
            const int col = colBase + wn * 32 + fn * 8 + tig * 2;
            if (col < N) {
                *(float2*)&C[(size_t)row * ldc + col] =
                    make_float2(acc[fm][fn][0], acc[fm][fn][1]);
                *(float2*)&C[(size_t)(row + 8) * ldc + col] =
                    make_float2(acc[fm][fn][2], acc[fm][fn][3]);
            }
        }
    }
}

// ---------------- fused flash attention (ldmatrix mainloop) ----------------
#define FBQ 128
#define FBK 64
#define FQP 200
#define FVP 72
#define FQ_SZ (FBQ*FQP)
#define FK_SZ (FBK*FQP)
#define FV_SZ (VHD_*FVP)
#define FSMEM ((FQ_SZ + 2*FK_SZ + 2*FV_SZ) * 2)

__global__ __launch_bounds__(256, 1) void flash_attn(float scale)
{
    extern __shared__ __half fsm[];
    __half* Qs  = fsm;
    __half* Ks0 = Qs + FQ_SZ;
    __half* Vs0 = Ks0 + 2 * FK_SZ;
    const uint32_t sQ = (uint32_t)__cvta_generic_to_shared(Qs);
    const uint32_t sK = (uint32_t)__cvta_generic_to_shared(Ks0);
    const uint32_t sV = (uint32_t)__cvta_generic_to_shared(Vs0);

    const int qt = (int)(gridDim.x - 1 - blockIdx.x);
    const int bh = blockIdx.y;
    const int qbase = qt * FBQ;
    const int tid = threadIdx.x;
    const int wid = tid >> 5, lane = tid & 31, g = lane >> 2, tig = lane & 3;
    const int qr0 = wid * 16;

    const __half* Qg = g_Qfh + ((size_t)bh * S_ + qbase) * QKD_;
    const __half* Kg = g_Kfh + (size_t)bh * S_ * QKD_;
    const __half* Vg = g_Vth + (size_t)bh * VHD_ * S_;

    {
        int r = tid >> 1, off = (tid & 1) * 96;
        const __half* src = Qg + (size_t)r * QKD_ + off;
        uint32_t dst = sQ + (uint32_t)(r * FQP + off) * 2u;
        #pragma unroll
        for (int c = 0; c < 12; c++) cp16(dst + c * 16, src + c * 8);
    }
    auto loadKV = [&](int st, int kt) {
        const int kbase = kt * FBK;
        {   int r = tid >> 2, off = (tid & 3) * 48;
            const __half* src = Kg + (size_t)(kbase + r) * QKD_ + off;
            uint32_t dst = sK + (uint32_t)(st * FK_SZ + r * FQP + off) * 2u;
            #pragma unroll
            for (int c = 0; c < 6; c++) cp16(dst + c * 16, src + c * 8);
        }
        {   int r = tid >> 1, off = (tid & 1) * 32;
            const __half* src = Vg + (size_t)r * S_ + kbase + off;
            uint32_t dst = sV + (uint32_t)(st * FV_SZ + r * FVP + off) * 2u;
            #pragma unroll
            for (int c = 0; c < 4; c++) cp16(dst + c * 16, src + c * 8);
        }
        cp_commit();
    };

    const int ktmax = (qbase + FBQ - 1) / FBK;
    loadKV(0, 0);

    float oacc[16][4];
    #pragma unroll
    for (int i = 0; i < 16; i++)
        #pragma unroll
        for (int j = 0; j < 4; j++) oacc[i][j] = 0.f;
    float sm0 = -1e30f, sm1 = -1e30f, l0 = 0.f, l1 = 0.f;

    const int row0 = qbase + qr0 + g;
    const int row1 = row0 + 8;

    // ldmatrix lane-address bases
    const uint32_t aQB = sQ + (uint32_t)(((qr0 + (lane & 15)) * FQP + (lane >> 4) * 8) * 2);
    const uint32_t bRow = (uint32_t)((lane & 7) + ((lane >> 4) & 1) * 8);
    const uint32_t bCol = (uint32_t)(((lane >> 3) & 1) * 8);
    const uint32_t bKB = (uint32_t)((bRow * FQP + bCol) * 2);
    const uint32_t bVB = (uint32_t)((bRow * FVP + bCol) * 2);

    for (int kt = 0; kt <= ktmax; kt++) {
        const int st = kt & 1;
        if (kt < ktmax) {
            loadKV(st ^ 1, kt + 1);
            asm volatile("cp.async.wait_group 1;\n" ::: "memory");
        } else {
            asm volatile("cp.async.wait_group 0;\n" ::: "memory");
        }
        __syncthreads();

        const int kbase = kt * FBK;
        if (kbase <= qbase + qr0 + 15) {
            const uint32_t kSt = sK + (uint32_t)(st * FK_SZ) * 2u + bKB;
            const uint32_t vSt = sV + (uint32_t)(st * FV_SZ) * 2u + bVB;

            float sacc[8][4];
            #pragma unroll
            for (int nb = 0; nb < 8; nb++)
                #pragma unroll
                for (int j = 0; j < 4; j++) sacc[nb][j] = 0.f;

            #pragma unroll
            for (int kc = 0; kc < 12; kc++) {
                const uint32_t kby = (uint32_t)(kc * 32);
                uint32_t a[4];
                ldsm_x4(a[0], a[1], a[2], a[3], aQB + kby);
                uint32_t b[8][2];
                #pragma unroll
                for (int np = 0; np < 4; np++)
                    ldsm_x4(b[2*np][0], b[2*np][1], b[2*np+1][0], b[2*np+1][1],
                            kSt + (uint32_t)(np * 16 * FQP) * 2u + kby);
                #pragma unroll
                for (int nb = 0; nb < 8; nb++)
                    mma_f16(sacc[nb], a, b[nb]);
            }

            const bool need_mask = (kbase + FBK - 1) > (qbase + qr0);
            #pragma unroll
            for (int nb = 0; nb < 8; nb++) {
                const int c0 = kbase + nb * 8 + 2 * tig, c1 = c0 + 1;
                sacc[nb][0] *= scale; sacc[nb][1] *= scale;
                sacc[nb][2] *= scale; sacc[nb][3] *= scale;
                if (need_mask) {
                    if (c0 > row0) sacc[nb][0] = -1e30f;
                    if (c1 > row0) sacc[nb][1] = -1e30f;
                    if (c0 > row1) sacc[nb][2] = -1e30f;
                    if (c1 > row1) sacc[nb][3] = -1e30f;
                }
            }

            float mx0 = -1e30f, mx1 = -1e30f;
            #pragma unroll
            for (int nb = 0; nb < 8; nb++) {
                mx0 = fmaxf(mx0, fmaxf(sacc[nb][0], sacc[nb][1]));
                mx1 = fmaxf(mx1, fmaxf(sacc[nb][2], sacc[nb][3]));
            }
            mx0 = fmaxf(mx0, __shfl_xor_sync(0xFFFFFFFFu, mx0, 1));
            mx0 = fmaxf(mx0, __shfl_xor_sync(0xFFFFFFFFu, mx0, 2));
            mx1 = fmaxf(mx1, __shfl_xor_sync(0xFFFFFFFFu, mx1, 1));
            mx1 = fmaxf(mx1, __shfl_xor_sync(0xFFFFFFFFu, mx1, 2));

            const float mn0 = fmaxf(sm0, mx0), mn1 = fmaxf(sm1, mx1);
            const float al0 = __expf(sm0 - mn0), al1 = __expf(sm1 - mn1);
            sm0 = mn0; sm1 = mn1;

            uint32_t pA[8], pB[8];
            float ps0 = 0.f, ps1 = 0.f;
            #pragma unroll
            for (int nb = 0; nb < 8; nb++) {
                const float e0 = __expf(sacc[nb][0] - mn0);
                const float e1 = __expf(sacc[nb][1] - mn0);
                const float e2 = __expf(sacc[nb][2] - mn1);
                const float e3 = __expf(sacc[nb][3] - mn1);
                ps0 += e0 + e1; ps1 += e2 + e3;
                pA[nb] = h2u(__floats2half2_rn(e0, e1));
                pB[nb] = h2u(__floats2half2_rn(e2, e3));
            }
            l0 = l0 * al0 + ps0;
            l1 = l1 * al1 + ps1;

            #pragma unroll
            for (int nb2 = 0; nb2 < 16; nb2++) {
                oacc[nb2][0] *= al0; oacc[nb2][1] *= al0;
                oacc[nb2][2] *= al1; oacc[nb2][3] *= al1;
            }

            #pragma unroll
            for (int kc = 0; kc < 4; kc++) {
                uint32_t a[4] = { pA[2*kc], pB[2*kc], pA[2*kc+1], pB[2*kc+1] };
                const uint32_t kby = (uint32_t)(kc * 32);
                uint32_t bv[16][2];
                #pragma unroll
                for (int np = 0; np < 8; np++)
                    ldsm_x4(bv[2*np][0], bv[2*np][1], bv[2*np+1][0], bv[2*np+1][1],
                            vSt + (uint32_t)(np * 16 * FVP) * 2u + kby);
                #pragma unroll
                for (int nb2 = 0; nb2 < 16; nb2++)
                    mma_f16(oacc[nb2], a, bv[nb2]);
            }
        }
        __syncthreads();
    }

    l0 += __shfl_xor_sync(0xFFFFFFFFu, l0, 1);
    l0 += __shfl_xor_sync(0xFFFFFFFFu, l0, 2);
    l1 += __shfl_xor_sync(0xFFFFFFFFu, l1, 1);
    l1 += __shfl_xor_sync(0xFFFFFFFFu, l1, 2);
    const float inv0 = 1.f / l0, inv1 = 1.f / l1;

    const int b = bh / H_, h = bh % H_;
    __half* out0 = g_ctxh + (size_t)(b * S_ + row0) * (H_*VHD_) + h * VHD_;
    __half* out1 = out0 + (size_t)8 * (H_*VHD_);
    #pragma unroll
    for (int nb2 = 0; nb2 < 16; nb2++) {
        const int d = nb2 * 8 + 2 * tig;
        *(__half2*)(out0 + d) = __floats2half2_rn(oacc[nb2][0] * inv0, oacc[nb2][1] * inv0);
        *(__half2*)(out1 + d) = __floats2half2_rn(oacc[nb2][2] * inv1, oacc[nb2][3] * inv1);
    }
}

// ---------------- converts ----------------
__global__ void cvt_h(const float* __restrict__ src, __half* __restrict__ dst, int n4) {
    int i = blockIdx.x * blockDim.x + threadIdx.x;
    if (i >= n4) return;
    float4 v = ((const float4*)src)[i];
    ((__half2*)dst)[2*i]   = __floats2half2_rn(v.x, v.y);
    ((__half2*)dst)[2*i+1] = __floats2half2_rn(v.z, v.w);
}

__global__ void transpose_h(const float* __restrict__ src, __half* __restrict__ dst,
                            int K, int N, int Npad)
{
    __shared__ float tile[32][33];
    const int k0 = blockIdx.y * 32, n0 = blockIdx.x * 32;
    const int tx = threadIdx.x, ty = threadIdx.y;
    #pragma unroll
    for (int i = ty; i < 32; i += 8) {
        int k = k0 + i, n = n0 + tx;
        tile[i][tx] = (k < K && n < N) ? src[(size_t)k * N + n] : 0.f;
    }
    __syncthreads();
    #pragma unroll
    for (int i = ty; i < 32; i += 8) {
        int n = n0 + i, k = k0 + tx;
        if (n < Npad && k < K) dst[(size_t)n * K + k] = __float2half(tile[tx][i]);
    }
}

// ---------------- reductions / rmsnorm ----------------
__device__ __forceinline__ float block_reduce_sum(float v, float* sbuf) {
    int tid = threadIdx.x;
    sbuf[tid] = v; __syncthreads();
    #pragma unroll
    for (int s = 128; s > 0; s >>= 1) {
        if (tid < s) sbuf[tid] = sbuf[tid] + sbuf[tid + s];
        __syncthreads();
    }
    float r = sbuf[0]; __syncthreads();
    return r;
}

__global__ __launch_bounds__(256) void rmsnorm_h(const float* __restrict__ x,
                                                 const float* __restrict__ w,
                                                 __half* __restrict__ y,
                                                 int n, int si, int so)
{
    __shared__ float sbuf[256];
    const size_t row = blockIdx.x;
    const float* xr = x + row * si;
    float acc = 0.f;
    for (int j = threadIdx.x; j < n; j += 256) { float v = xr[j]; acc += v * v; }
    float tot = block_reduce_sum(acc, sbuf);
    float scale = rsqrtf(tot / (float)n + EPS_);
    __half* yr = y + row * so;
    for (int j = threadIdx.x; j < n; j += 256) yr[j] = __float2half(xr[j] * scale * w[j]);
}

// ---------------- RoPE + assembly ----------------
__global__ void build_cs(const int* __restrict__ pos) {
    int idx = blockIdx.x * blockDim.x + threadIdx.x;
    if (idx >= TOK_ * 32) return;
    int j = idx & 31, tok = idx >> 5;
    float inv = powf(10000.f, -((float)(2 * j)) / 64.f);
    float ang = (float)pos[tok] * inv;
    g_cos[idx] = cosf(ang);
    g_sin[idx] = sinf(ang);
}

__device__ __forceinline__ float rope_val(const float* pair_base, int drel, int tok) {
    int j = drel >> 1;
    float c = g_cos[tok * 32 + j], s = g_sin[tok * 32 + j];
    float ev = pair_base[2*j], ov = pair_base[2*j + 1];
    return ((drel & 1) == 0) ? (ev * c - ov * s) : (ov * c + ev * s);
}

__global__ void build_q() {
    int idx = blockIdx.x * blockDim.x + threadIdx.x;
    if (idx >= BH_ * S_ * QKD_) return;
    int d  = idx % QKD_;
    int r  = idx / QKD_;
    int s  = r % S_;
    int bh = r / S_;
    int b = bh / H_, h = bh % H_;
    int tok = b * S_ + s;
    const float* src = g_q + (size_t)tok * (H_*QKD_) + h * QKD_;
    float v;
    if (d < NOPE_) v = src[d];
    else           v = rope_val(src + NOPE_, d - NOPE_, tok);
    g_Qfh[idx] = __float2half(v);
}

__global__ void build_k() {
    int idx = blockIdx.x * blockDim.x + threadIdx.x;
    if (idx >= BH_ * S_ * QKD_) return;
    int d  = idx % QKD_;
    int r  = idx / QKD_;
    int s  = r % S_;
    int bh = r / S_;
    int b = bh / H_, h = bh % H_;
    int tok = b * S_ + s;
    float v;
    if (d < NOPE_) v = g_kv[(size_t)tok * (H_*(NOPE_+VHD_)) + h * (NOPE_+VHD_) + d];
    else           v = rope_val(g_kvc + (size_t)tok * KVO_ + KVR_, d - NOPE_, tok);
    g_Kfh[idx] = __float2half(v);
}

__global__ void build_vt() {
    int idx = blockIdx.x * blockDim.x + threadIdx.x;
    if (idx >= BH_ * VHD_ * S_) return;
    int s  = idx % S_;
    int r  = idx / S_;
    int d  = r % VHD_;
    int bh = r / VHD_;
    int b = bh / H_, h = bh % H_;
    int tok = b * S_ + s;
    g_Vth[idx] = __float2half(g_kv[(size_t)tok * (H_*(NOPE_+VHD_)) + h * (NOPE_+VHD_) + NOPE_ + d]);
}

// ---------------- launcher ----------------
extern "C" void kernel_launch(void* const* d_in, const int* in_sizes, int n_in,
                              void* d_out, int out_size)
{
    const float* hs    = (const float*)d_in[0];
    const float* Wq_a  = (const float*)d_in[1];
    const float* q_ln  = (const float*)d_in[2];
    const float* Wq_b  = (const float*)d_in[3];
    const float* Wkv_a = (const float*)d_in[4];
    const float* kv_ln = (const float*)d_in[5];
    const float* Wkv_b = (const float*)d_in[6];
    const float* Wo    = (const float*)d_in[7];
    const int*   pos   = (const int*)  d_in[8];
    float* out = (float*)d_out;

    float *p_qa, *p_q, *p_kvc, *p_kv;
    __half *p_qah, *p_kvnh, *p_Qfh, *p_Kfh, *p_Vth, *p_ctxh;
    __half *p_hsch, *p_wqah, *p_wqbh, *p_wkvah, *p_wkvbh, *p_woh;
    cudaGetSymbolAddress((void**)&p_qa,   g_qa);
    cudaGetSymbolAddress((void**)&p_qah,  g_qah);
    cudaGetSymbolAddress((void**)&p_q,    g_q);
    cudaGetSymbolAddress((void**)&p_kvc,  g_kvc);
    cudaGetSymbolAddress((void**)&p_kvnh, g_kvnh);
    cudaGetSymbolAddress((void**)&p_kv,   g_kv);
    cudaGetSymbolAddress((void**)&p_Qfh,  g_Qfh);
    cudaGetSymbolAddress((void**)&p_Kfh,  g_Kfh);
    cudaGetSymbolAddress((void**)&p_Vth,  g_Vth);
    cudaGetSymbolAddress((void**)&p_ctxh, g_ctxh);
    cudaGetSymbolAddress((void**)&p_hsch, g_hsch);
    cudaGetSymbolAddress((void**)&p_wqah, g_wqah);
    cudaGetSymbolAddress((void**)&p_wqbh, g_wqbh);
    cudaGetSymbolAddress((void**)&p_wkvah,g_wkvah);
    cudaGetSymbolAddress((void**)&p_wkvbh,g_wkvbh);
    cudaGetSymbolAddress((void**)&p_woh,  g_woh);

    static bool attr_done = false;
    if (!attr_done) {
        cudaFuncSetAttribute(hgemm, cudaFuncAttributeMaxDynamicSharedMemorySize, SMEM_H);
        cudaFuncSetAttribute(flash_attn, cudaFuncAttributeMaxDynamicSharedMemorySize, FSMEM);
        attr_done = true;
    }

    cvt_h<<<(TOK_*IN_/4 + 255)/256, 256>>>(hs, p_hsch, TOK_*IN_/4);
    dim3 tb(32, 8);
    transpose_h<<<dim3(QR_/32, IN_/32), tb>>>(Wq_a, p_wqah, IN_, QR_, QR_);
    transpose_h<<<dim3((H_*QKD_)/32, QR_/32), tb>>>(Wq_b, p_wqbh, QR_, H_*QKD_, H_*QKD_);
    transpose_h<<<dim3(KVAP_/32, IN_/32), tb>>>(Wkv_a, p_wkvah, IN_, KVO_, KVAP_);
    transpose_h<<<dim3((H_*(NOPE_+VHD_))/32, KVR_/32), tb>>>(Wkv_b, p_wkvbh,
                                                             KVR_, H_*(NOPE_+VHD_), H_*(NOPE_+VHD_));
    transpose_h<<<dim3(HID_/32, HID_/32), tb>>>(Wo, p_woh, HID_, HID_, HID_);

    hgemm<<<dim3(QR_/128, TOK_/128), 256, SMEM_H>>>(
        p_hsch, p_wqah, p_qa, TOK_, QR_, IN_, IN_, IN_, QR_);
    rmsnorm_h<<<TOK_, 256>>>(p_qa, q_ln, p_qah, QR_, QR_, QR_);
    hgemm<<<dim3((H_*QKD_)/128, TOK_/128), 256, SMEM_H>>>(
        p_qah, p_wqbh, p_q, TOK_, H_*QKD_, QR_, QR_, QR_, H_*QKD_);

    hgemm<<<dim3(KVAP_/128, TOK_/128), 256, SMEM_H>>>(
        p_hsch, p_wkvah, p_kvc, TOK_, KVO_, IN_, IN_, IN_, KVO_);
    rmsnorm_h<<<TOK_, 256>>>(p_kvc, kv_ln, p_kvnh, KVR_, KVO_, KVR_);
    hgemm<<<dim3((H_*(NOPE_+VHD_))/128, TOK_/128), 256, SMEM_H>>>(
        p_kvnh, p_wkvbh, p_kv, TOK_, H_*(NOPE_+VHD_), KVR_, KVR_, KVR_, H_*(NOPE_+VHD_));

    build_cs<<<(TOK_*32 + 255)/256, 256>>>(pos);
    int nq = BH_ * S_ * QKD_;
    build_q<<<(nq + 255) / 256, 256>>>();
    build_k<<<(nq + 255) / 256, 256>>>();
    int nv = BH_ * VHD_ * S_;
    build_vt<<<(nv + 255) / 256, 256>>>();

    float scale = 1.f / sqrtf((float)QKD_);
    flash_attn<<<dim3(S_/FBQ, BH_), 256, FSMEM>>>(scale);

    hgemm<<<dim3(HID_/128, TOK_/128), 256, SMEM_H>>>(
        p_ctxh, p_woh, out, TOK_, HID_, HID_, HID_, HID_, HID_);
}

// round 11
// speedup vs baseline: 2.1654x; 1.0792x over previous
#include <cuda_runtime.h>
#include <cuda_fp16.h>
#include <math.h>
#include <stdint.h>

// ---------------- problem constants ----------------
#define B_    2
#define S_    2048
#define HID_  2048
#define IN_   4096
#define H_    16
#define NOPE_ 128
#define ROPE_ 64
#define VHD_  128
#define QKD_  192
#define QR_   1536
#define KVR_  512
#define TOK_  (B_*S_)
#define BH_   (B_*H_)
#define EPS_  1e-6f
#define KVO_  (KVR_+ROPE_)   // 576
#define NQKV_ (QR_+KVO_)     // 2112 (merged qa+kva output cols)
#define NQKVP_ 2176          // padded to 128-multiple

// ---------------- scratch ----------------
__device__ float  g_qa  [TOK_*QR_];
__device__ __half g_qah [TOK_*QR_];
__device__ float  g_q   [TOK_*(H_*QKD_)];
__device__ float  g_kvc [TOK_*KVO_];
__device__ __half g_kvnh[TOK_*KVR_];
__device__ __half g_kvh [TOK_*(H_*(NOPE_+VHD_))];  // kvb out, half
__device__ __half g_Qfh [BH_*S_*QKD_];
__device__ __half g_Kfh [BH_*S_*QKD_];
__device__ __half g_Vth [BH_*VHD_*S_];             // V^T [bh][d][s]
__device__ __half g_ctxh[TOK_*(H_*VHD_)];
__device__ float  g_cos [TOK_*32];
__device__ float  g_sin [TOK_*32];
__device__ __half g_hsch  [TOK_*IN_];
__device__ __half g_wqkvh [NQKVP_*IN_];            // [Wq_a^T ; Wkv_a^T]
__device__ __half g_wqbh  [(H_*QKD_)*QR_];
__device__ __half g_wkvbh [(H_*(NOPE_+VHD_))*KVR_];
__device__ __half g_woh   [HID_*HID_];

// ---------------- helpers ----------------
__device__ __forceinline__ void mma_f16(float c[4], const uint32_t a[4], const uint32_t b[2]) {
    asm volatile(
        "mma.sync.aligned.m16n8k16.row.col.f32.f16.f16.f32 "
        "{%0,%1,%2,%3}, {%4,%5,%6,%7}, {%8,%9}, {%0,%1,%2,%3};"
        : "+f"(c[0]), "+f"(c[1]), "+f"(c[2]), "+f"(c[3])
        : "r"(a[0]), "r"(a[1]), "r"(a[2]), "r"(a[3]), "r"(b[0]), "r"(b[1]));
}
__device__ __forceinline__ void ldsm_x4(uint32_t& r0, uint32_t& r1, uint32_t& r2, uint32_t& r3,
                                        uint32_t addr) {
    asm volatile("ldmatrix.sync.aligned.m8n8.x4.shared.b16 {%0,%1,%2,%3}, [%4];"
                 : "=r"(r0), "=r"(r1), "=r"(r2), "=r"(r3) : "r"(addr));
}
__device__ __forceinline__ void cp16(uint32_t dst, const void* src) {
    asm volatile("cp.async.cg.shared.global [%0], [%1], 16;\n" :: "r"(dst), "l"(src));
}
__device__ __forceinline__ void cp_commit() {
    asm volatile("cp.async.commit_group;\n" ::: "memory");
}
__device__ __forceinline__ uint32_t h2u(__half2 h) { return *(uint32_t*)&h; }

// ---------------- dense fp16 TB GEMM, ldmatrix mainloop ----------------
// MODE: 0 = fp32 out; 1 = half out; 2 = split fp32 out (C cols<nsplit, C2 rest)
#define HBK 32
#define HP  40
#define H_STG (128*HP)
#define HSTG  4
#define SMEM_H (HSTG * 2 * H_STG * 2)

template<int MODE>
__global__ __launch_bounds__(256, 2) void hgemm(
    const __half* __restrict__ A, const __half* __restrict__ B,
    float* __restrict__ C, __half* __restrict__ Ch,
    float* __restrict__ C2, int ldc2, int nsplit,
    int M, int N, int K, int lda, int ldb, int ldc)
{
    extern __shared__ __half hsm[];
    __half* Asm = hsm;
    __half* Bsm = hsm + HSTG * H_STG;
    const uint32_t sA32 = (uint32_t)__cvta_generic_to_shared(Asm);
    const uint32_t sB32 = (uint32_t)__cvta_generic_to_shared(Bsm);

    const int nt = K / HBK;
    const int tid  = threadIdx.x;
    const int lane = tid & 31;
    const int g    = lane >> 2;
    const int tig  = lane & 3;
    const int wid  = tid >> 5;
    const int wm   = wid & 1;
    const int wn   = wid >> 1;
    const int rowBase = blockIdx.y * 128;
    const int colBase = blockIdx.x * 128;

    const int r  = tid >> 1;
    const int co = (tid & 1) << 4;
    const __half* Ap = A + (size_t)(rowBase + r) * lda + co;
    const __half* Bp = B + (size_t)(colBase + r) * ldb + co;
    const uint32_t a_dst = sA32 + (uint32_t)(r * HP + co) * 2u;
    const uint32_t b_dst = sB32 + (uint32_t)(r * HP + co) * 2u;

    auto load_stage = [&](int st, int kc) {
        const uint32_t so = (uint32_t)(st * H_STG) * 2u;
        const __half* as = Ap + kc * HBK;
        const __half* bs = Bp + kc * HBK;
        cp16(a_dst + so,      as);
        cp16(a_dst + so + 16, as + 8);
        cp16(b_dst + so,      bs);
        cp16(b_dst + so + 16, bs + 8);
        cp_commit();
    };

    const uint32_t aLB = (uint32_t)(((wm * 64 + (lane & 15)) * HP + (lane >> 4) * 8) * 2);
    const uint32_t bLB = (uint32_t)(((wn * 32 + (lane & 7) + ((lane >> 4) & 1) * 8) * HP
                                     + ((lane >> 3) & 1) * 8) * 2);

    float acc[4][4][4];
    #pragma unroll
    for (int i = 0; i < 4; i++)
        #pragma unroll
        for (int j = 0; j < 4; j++)
            #pragma unroll
            for (int q = 0; q < 4; q++) acc[i][j][q] = 0.f;

    #pragma unroll
    for (int s = 0; s < HSTG - 1; s++) {
        if (s < nt) load_stage(s, s);
        else        cp_commit();
    }

    for (int t = 0; t < nt; t++) {
        asm volatile("cp.async.wait_group 2;\n" ::: "memory");
        __syncthreads();

        const int tn = t + HSTG - 1;
        if (tn < nt) load_stage(tn % HSTG, tn);
        else         cp_commit();

        const uint32_t stoff = (uint32_t)((t % HSTG) * H_STG) * 2u;
        const uint32_t aSt = sA32 + stoff + aLB;
        const uint32_t bSt = sB32 + stoff + bLB;

        #pragma unroll
        for (int ks = 0; ks < 2; ks++) {
            const uint32_t kby = (uint32_t)(ks * 32);
            uint32_t afr[4][4], bfr[4][2];
            #pragma unroll
            for (int fm = 0; fm < 4; fm++)
                ldsm_x4(afr[fm][0], afr[fm][1], afr[fm][2], afr[fm][3],
                        aSt + (uint32_t)(fm * 16 * HP) * 2u + kby);
            #pragma unroll
            for (int fp = 0; fp < 2; fp++)
                ldsm_x4(bfr[2*fp][0], bfr[2*fp][1], bfr[2*fp+1][0], bfr[2*fp+1][1],
                        bSt + (uint32_t)(fp * 16 * HP) * 2u + kby);
            #pragma unroll
            for (int fm = 0; fm < 4; fm++)
                #pragma unroll
                for (int fn = 0; fn < 4; fn++)
                    mma_f16(acc[fm][fn], afr[fm], bfr[fn]);
        }
    }

    #pragma unroll
    for (int fm = 0; fm < 4; fm++) {
        #pragma unroll
        for (int fn = 0; fn < 4; fn++) {
            const int row = rowBase + wm * 64 + fm * 16 + g;
            const int col = colBase + wn * 32 + fn * 8 + tig * 2;
            if (col < N) {
                if (MODE == 1) {
                    *(__half2*)&Ch[(size_t)row * ldc + col] =
                        __floats2half2_rn(acc[fm][fn][0], acc[fm][fn][1]);
                    *(__half2*)&Ch[(size_t)(row + 8) * ldc + col] =
                        __floats2half2_rn(acc[fm][fn][2], acc[fm][fn][3]);
                } else if (MODE == 2) {
                    if (col < nsplit) {
                        *(float2*)&C[(size_t)row * ldc + col] =
                            make_float2(acc[fm][fn][0], acc[fm][fn][1]);
                        *(float2*)&C[(size_t)(row + 8) * ldc + col] =
                            make_float2(acc[fm][fn][2], acc[fm][fn][3]);
                    } else {
                        const int c2 = col - nsplit;
                        *(float2*)&C2[(size_t)row * ldc2 + c2] =
                            make_float2(acc[fm][fn][0], acc[fm][fn][1]);
                        *(float2*)&C2[(size_t)(row + 8) * ldc2 + c2] =
                            make_float2(acc[fm][fn][2], acc[fm][fn][3]);
                    }
                } else {
                    *(float2*)&C[(size_t)row * ldc + col] =
                        make_float2(acc[fm][fn][0], acc[fm][fn][1]);
                    *(float2*)&C[(size_t)(row + 8) * ldc + col] =
                        make_float2(acc[fm][fn][2], acc[fm][fn][3]);
                }
            }
        }
    }
}

// ---------------- fused flash attention (ldmatrix mainloop) ----------------
#define FBQ 128
#define FBK 64
#define FQP 200
#define FVP 72
#define FQ_SZ (FBQ*FQP)
#define FK_SZ (FBK*FQP)
#define FV_SZ (VHD_*FVP)
#define FSMEM ((FQ_SZ + 2*FK_SZ + 2*FV_SZ) * 2)

__global__ __launch_bounds__(256, 1) void flash_attn(float scale)
{
    extern __shared__ __half fsm[];
    __half* Qs  = fsm;
    __half* Ks0 = Qs + FQ_SZ;
    __half* Vs0 = Ks0 + 2 * FK_SZ;
    const uint32_t sQ = (uint32_t)__cvta_generic_to_shared(Qs);
    const uint32_t sK = (uint32_t)__cvta_generic_to_shared(Ks0);
    const uint32_t sV = (uint32_t)__cvta_generic_to_shared(Vs0);

    const int qt = (int)(gridDim.x - 1 - blockIdx.x);
    const int bh = blockIdx.y;
    const int qbase = qt * FBQ;
    const int tid = threadIdx.x;
    const int wid = tid >> 5, lane = tid & 31, g = lane >> 2, tig = lane & 3;
    const int qr0 = wid * 16;

    const __half* Qg = g_Qfh + ((size_t)bh * S_ + qbase) * QKD_;
    const __half* Kg = g_Kfh + (size_t)bh * S_ * QKD_;
    const __half* Vg = g_Vth + (size_t)bh * VHD_ * S_;

    {
        int r = tid >> 1, off = (tid & 1) * 96;
        const __half* src = Qg + (size_t)r * QKD_ + off;
        uint32_t dst = sQ + (uint32_t)(r * FQP + off) * 2u;
        #pragma unroll
        for (int c = 0; c < 12; c++) cp16(dst + c * 16, src + c * 8);
    }
    auto loadKV = [&](int st, int kt) {
        const int kbase = kt * FBK;
        {   int r = tid >> 2, off = (tid & 3) * 48;
            const __half* src = Kg + (size_t)(kbase + r) * QKD_ + off;
            uint32_t dst = sK + (uint32_t)(st * FK_SZ + r * FQP + off) * 2u;
            #pragma unroll
            for (int c = 0; c < 6; c++) cp16(dst + c * 16, src + c * 8);
        }
        {   int r = tid >> 1, off = (tid & 1) * 32;
            const __half* src = Vg + (size_t)r * S_ + kbase + off;
            uint32_t dst = sV + (uint32_t)(st * FV_SZ + r * FVP + off) * 2u;
            #pragma unroll
            for (int c = 0; c < 4; c++) cp16(dst + c * 16, src + c * 8);
        }
        cp_commit();
    };

    const int ktmax = (qbase + FBQ - 1) / FBK;
    loadKV(0, 0);

    float oacc[16][4];
    #pragma unroll
    for (int i = 0; i < 16; i++)
        #pragma unroll
        for (int j = 0; j < 4; j++) oacc[i][j] = 0.f;
    float sm0 = -1e30f, sm1 = -1e30f, l0 = 0.f, l1 = 0.f;

    const int row0 = qbase + qr0 + g;
    const int row1 = row0 + 8;

    const uint32_t aQB = sQ + (uint32_t)(((qr0 + (lane & 15)) * FQP + (lane >> 4) * 8) * 2);
    const uint32_t bRow = (uint32_t)((lane & 7) + ((lane >> 4) & 1) * 8);
    const uint32_t bCol = (uint32_t)(((lane >> 3) & 1) * 8);
    const uint32_t bKB = (uint32_t)((bRow * FQP + bCol) * 2);
    const uint32_t bVB = (uint32_t)((bRow * FVP + bCol) * 2);

    for (int kt = 0; kt <= ktmax; kt++) {
        const int st = kt & 1;
        if (kt < ktmax) {
            loadKV(st ^ 1, kt + 1);
            asm volatile("cp.async.wait_group 1;\n" ::: "memory");
        } else {
            asm volatile("cp.async.wait_group 0;\n" ::: "memory");
        }
        __syncthreads();

        const int kbase = kt * FBK;
        if (kbase <= qbase + qr0 + 15) {
            const uint32_t kSt = sK + (uint32_t)(st * FK_SZ) * 2u + bKB;
            const uint32_t vSt = sV + (uint32_t)(st * FV_SZ) * 2u + bVB;

            float sacc[8][4];
            #pragma unroll
            for (int nb = 0; nb < 8; nb++)
                #pragma unroll
                for (int j = 0; j < 4; j++) sacc[nb][j] = 0.f;

            #pragma unroll
            for (int kc = 0; kc < 12; kc++) {
                const uint32_t kby = (uint32_t)(kc * 32);
                uint32_t a[4];
                ldsm_x4(a[0], a[1], a[2], a[3], aQB + kby);
                uint32_t b[8][2];
                #pragma unroll
                for (int np = 0; np < 4; np++)
                    ldsm_x4(b[2*np][0], b[2*np][1], b[2*np+1][0], b[2*np+1][1],
                            kSt + (uint32_t)(np * 16 * FQP) * 2u + kby);
                #pragma unroll
                for (int nb = 0; nb < 8; nb++)
                    mma_f16(sacc[nb], a, b[nb]);
            }

            const bool need_mask = (kbase + FBK - 1) > (qbase + qr0);
            #pragma unroll
            for (int nb = 0; nb < 8; nb++) {
                const int c0 = kbase + nb * 8 + 2 * tig, c1 = c0 + 1;
                sacc[nb][0] *= scale; sacc[nb][1] *= scale;
                sacc[nb][2] *= scale; sacc[nb][3] *= scale;
                if (need_mask) {
                    if (c0 > row0) sacc[nb][0] = -1e30f;
                    if (c1 > row0) sacc[nb][1] = -1e30f;
                    if (c0 > row1) sacc[nb][2] = -1e30f;
                    if (c1 > row1) sacc[nb][3] = -1e30f;
                }
            }

            float mx0 = -1e30f, mx1 = -1e30f;
            #pragma unroll
            for (int nb = 0; nb < 8; nb++) {
                mx0 = fmaxf(mx0, fmaxf(sacc[nb][0], sacc[nb][1]));
                mx1 = fmaxf(mx1, fmaxf(sacc[nb][2], sacc[nb][3]));
            }
            mx0 = fmaxf(mx0, __shfl_xor_sync(0xFFFFFFFFu, mx0, 1));
            mx0 = fmaxf(mx0, __shfl_xor_sync(0xFFFFFFFFu, mx0, 2));
            mx1 = fmaxf(mx1, __shfl_xor_sync(0xFFFFFFFFu, mx1, 1));
            mx1 = fmaxf(mx1, __shfl_xor_sync(0xFFFFFFFFu, mx1, 2));

            const float mn0 = fmaxf(sm0, mx0), mn1 = fmaxf(sm1, mx1);
            const float al0 = __expf(sm0 - mn0), al1 = __expf(sm1 - mn1);
            sm0 = mn0; sm1 = mn1;

            uint32_t pA[8], pB[8];
            float ps0 = 0.f, ps1 = 0.f;
            #pragma unroll
            for (int nb = 0; nb < 8; nb++) {
                const float e0 = __expf(sacc[nb][0] - mn0);
                const float e1 = __expf(sacc[nb][1] - mn0);
                const float e2 = __expf(sacc[nb][2] - mn1);
                const float e3 = __expf(sacc[nb][3] - mn1);
                ps0 += e0 + e1; ps1 += e2 + e3;
                pA[nb] = h2u(__floats2half2_rn(e0, e1));
                pB[nb] = h2u(__floats2half2_rn(e2, e3));
            }
            l0 = l0 * al0 + ps0;
            l1 = l1 * al1 + ps1;

            #pragma unroll
            for (int nb2 = 0; nb2 < 16; nb2++) {
                oacc[nb2][0] *= al0; oacc[nb2][1] *= al0;
                oacc[nb2][2] *= al1; oacc[nb2][3] *= al1;
            }

            #pragma unroll
            for (int kc = 0; kc < 4; kc++) {
                uint32_t a[4] = { pA[2*kc], pB[2*kc], pA[2*kc+1], pB[2*kc+1] };
                const uint32_t kby = (uint32_t)(kc * 32);
                uint32_t bv[16][2];
                #pragma unroll
                for (int np = 0; np < 8; np++)
                    ldsm_x4(bv[2*np][0], bv[2*np][1], bv[2*np+1][0], bv[2*np+1][1],
                            vSt + (uint32_t)(np * 16 * FVP) * 2u + kby);
                #pragma unroll
                for (int nb2 = 0; nb2 < 16; nb2++)
                    mma_f16(oacc[nb2], a, bv[nb2]);
            }
        }
        __syncthreads();
    }

    l0 += __shfl_xor_sync(0xFFFFFFFFu, l0, 1);
    l0 += __shfl_xor_sync(0xFFFFFFFFu, l0, 2);
    l1 += __shfl_xor_sync(0xFFFFFFFFu, l1, 1);
    l1 += __shfl_xor_sync(0xFFFFFFFFu, l1, 2);
    const float inv0 = 1.f / l0, inv1 = 1.f / l1;

    const int b = bh / H_, h = bh % H_;
    __half* out0 = g_ctxh + (size_t)(b * S_ + row0) * (H_*VHD_) + h * VHD_;
    __half* out1 = out0 + (size_t)8 * (H_*VHD_);
    #pragma unroll
    for (int nb2 = 0; nb2 < 16; nb2++) {
        const int d = nb2 * 8 + 2 * tig;
        *(__half2*)(out0 + d) = __floats2half2_rn(oacc[nb2][0] * inv0, oacc[nb2][1] * inv0);
        *(__half2*)(out1 + d) = __floats2half2_rn(oacc[nb2][2] * inv1, oacc[nb2][3] * inv1);
    }
}

// ---------------- converts ----------------
__global__ void cvt_h(const float* __restrict__ src, __half* __restrict__ dst, int n4) {
    int i = blockIdx.x * blockDim.x + threadIdx.x;
    if (i >= n4) return;
    float4 v = ((const float4*)src)[i];
    ((__half2*)dst)[2*i]   = __floats2half2_rn(v.x, v.y);
    ((__half2*)dst)[2*i+1] = __floats2half2_rn(v.z, v.w);
}

__global__ void transpose_h(const float* __restrict__ src, __half* __restrict__ dst,
                            int K, int N, int Npad)
{
    __shared__ float tile[32][33];
    const int k0 = blockIdx.y * 32, n0 = blockIdx.x * 32;
    const int tx = threadIdx.x, ty = threadIdx.y;
    #pragma unroll
    for (int i = ty; i < 32; i += 8) {
        int k = k0 + i, n = n0 + tx;
        tile[i][tx] = (k < K && n < N) ? src[(size_t)k * N + n] : 0.f;
    }
    __syncthreads();
    #pragma unroll
    for (int i = ty; i < 32; i += 8) {
        int n = n0 + i, k = k0 + tx;
        if (n < Npad && k < K) dst[(size_t)n * K + k] = __float2half(tile[tx][i]);
    }
}

// ---------------- fused rmsnorm for both paths ----------------
__device__ __forceinline__ float block_reduce_sum(float v, float* sbuf) {
    int tid = threadIdx.x;
    sbuf[tid] = v; __syncthreads();
    #pragma unroll
    for (int s = 128; s > 0; s >>= 1) {
        if (tid < s) sbuf[tid] = sbuf[tid] + sbuf[tid + s];
        __syncthreads();
    }
    float r = sbuf[0]; __syncthreads();
    return r;
}

__global__ __launch_bounds__(256) void rms_both(const float* __restrict__ q_ln,
                                                const float* __restrict__ kv_ln)
{
    __shared__ float sbuf[256];
    const int row = blockIdx.x;
    const float* xr;
    const float* w;
    __half* yr;
    int n;
    if (row < TOK_) {
        xr = g_qa + (size_t)row * QR_; w = q_ln; yr = g_qah + (size_t)row * QR_; n = QR_;
    } else {
        int r = row - TOK_;
        xr = g_kvc + (size_t)r * KVO_; w = kv_ln; yr = g_kvnh + (size_t)r * KVR_; n = KVR_;
    }
    float acc = 0.f;
    for (int j = threadIdx.x; j < n; j += 256) { float v = xr[j]; acc += v * v; }
    float tot = block_reduce_sum(acc, sbuf);
    float scale = rsqrtf(tot / (float)n + EPS_);
    for (int j = threadIdx.x; j < n; j += 256) yr[j] = __float2half(xr[j] * scale * w[j]);
}

// ---------------- RoPE + assembly ----------------
__global__ void build_cs(const int* __restrict__ pos) {
    int idx = blockIdx.x * blockDim.x + threadIdx.x;
    if (idx >= TOK_ * 32) return;
    int j = idx & 31, tok = idx >> 5;
    float inv = powf(10000.f, -((float)(2 * j)) / 64.f);
    float ang = (float)pos[tok] * inv;
    g_cos[idx] = cosf(ang);
    g_sin[idx] = sinf(ang);
}

__device__ __forceinline__ float rope_val(const float* pair_base, int drel, int tok) {
    int j = drel >> 1;
    float c = g_cos[tok * 32 + j], s = g_sin[tok * 32 + j];
    float ev = pair_base[2*j], ov = pair_base[2*j + 1];
    return ((drel & 1) == 0) ? (ev * c - ov * s) : (ov * c + ev * s);
}

__global__ void build_q() {
    int idx = blockIdx.x * blockDim.x + threadIdx.x;
    if (idx >= BH_ * S_ * QKD_) return;
    int d  = idx % QKD_;
    int r  = idx / QKD_;
    int s  = r % S_;
    int bh = r / S_;
    int b = bh / H_, h = bh % H_;
    int tok = b * S_ + s;
    const float* src = g_q + (size_t)tok * (H_*QKD_) + h * QKD_;
    float v;
    if (d < NOPE_) v = src[d];
    else           v = rope_val(src + NOPE_, d - NOPE_, tok);
    g_Qfh[idx] = __float2half(v);
}

__global__ void build_k() {
    int idx = blockIdx.x * blockDim.x + threadIdx.x;
    if (idx >= BH_ * S_ * QKD_) return;
    int d  = idx % QKD_;
    int r  = idx / QKD_;
    int s  = r % S_;
    int bh = r / S_;
    int b = bh / H_, h = bh % H_;
    int tok = b * S_ + s;
    __half v;
    if (d < NOPE_) v = g_kvh[(size_t)tok * (H_*(NOPE_+VHD_)) + h * (NOPE_+VHD_) + d];
    else           v = __float2half(rope_val(g_kvc + (size_t)tok * KVO_ + KVR_,
                                             d - NOPE_, tok));
    g_Kfh[idx] = v;
}

__global__ void build_vt() {
    int idx = blockIdx.x * blockDim.x + threadIdx.x;
    if (idx >= BH_ * VHD_ * S_) return;
    int s  = idx % S_;
    int r  = idx / S_;
    int d  = r % VHD_;
    int bh = r / VHD_;
    int b = bh / H_, h = bh % H_;
    int tok = b * S_ + s;
    g_Vth[idx] = g_kvh[(size_t)tok * (H_*(NOPE_+VHD_)) + h * (NOPE_+VHD_) + NOPE_ + d];
}

// ---------------- launcher ----------------
extern "C" void kernel_launch(void* const* d_in, const int* in_sizes, int n_in,
                              void* d_out, int out_size)
{
    const float* hs    = (const float*)d_in[0];
    const float* Wq_a  = (const float*)d_in[1];
    const float* q_ln  = (const float*)d_in[2];
    const float* Wq_b  = (const float*)d_in[3];
    const float* Wkv_a = (const float*)d_in[4];
    const float* kv_ln = (const float*)d_in[5];
    const float* Wkv_b = (const float*)d_in[6];
    const float* Wo    = (const float*)d_in[7];
    const int*   pos   = (const int*)  d_in[8];
    float* out = (float*)d_out;

    float *p_qa, *p_q, *p_kvc;
    __half *p_qah, *p_kvnh, *p_kvh, *p_ctxh;
    __half *p_hsch, *p_wqkvh, *p_wqbh, *p_wkvbh, *p_woh;
    cudaGetSymbolAddress((void**)&p_qa,    g_qa);
    cudaGetSymbolAddress((void**)&p_qah,   g_qah);
    cudaGetSymbolAddress((void**)&p_q,     g_q);
    cudaGetSymbolAddress((void**)&p_kvc,   g_kvc);
    cudaGetSymbolAddress((void**)&p_kvnh,  g_kvnh);
    cudaGetSymbolAddress((void**)&p_kvh,   g_kvh);
    cudaGetSymbolAddress((void**)&p_ctxh,  g_ctxh);
    cudaGetSymbolAddress((void**)&p_hsch,  g_hsch);
    cudaGetSymbolAddress((void**)&p_wqkvh, g_wqkvh);
    cudaGetSymbolAddress((void**)&p_wqbh,  g_wqbh);
    cudaGetSymbolAddress((void**)&p_wkvbh, g_wkvbh);
    cudaGetSymbolAddress((void**)&p_woh,   g_woh);

    static bool attr_done = false;
    if (!attr_done) {
        cudaFuncSetAttribute(hgemm<0>, cudaFuncAttributeMaxDynamicSharedMemorySize, SMEM_H);
        cudaFuncSetAttribute(hgemm<1>, cudaFuncAttributeMaxDynamicSharedMemorySize, SMEM_H);
        cudaFuncSetAttribute(hgemm<2>, cudaFuncAttributeMaxDynamicSharedMemorySize, SMEM_H);
        cudaFuncSetAttribute(flash_attn, cudaFuncAttributeMaxDynamicSharedMemorySize, FSMEM);
        attr_done = true;
    }

    // convert inputs (weights transposed to [N,K]); Wq_a/Wkv_a concatenated
    cvt_h<<<(TOK_*IN_/4 + 255)/256, 256>>>(hs, p_hsch, TOK_*IN_/4);
    dim3 tb(32, 8);
    transpose_h<<<dim3(QR_/32, IN_/32), tb>>>(Wq_a, p_wqkvh, IN_, QR_, QR_);
    transpose_h<<<dim3((KVO_+31)/32, IN_/32), tb>>>(Wkv_a, p_wqkvh + (size_t)QR_*IN_,
                                                    IN_, KVO_, KVO_);
    transpose_h<<<dim3((H_*QKD_)/32, QR_/32), tb>>>(Wq_b, p_wqbh, QR_, H_*QKD_, H_*QKD_);
    transpose_h<<<dim3((H_*(NOPE_+VHD_))/32, KVR_/32), tb>>>(Wkv_b, p_wkvbh,
                                                             KVR_, H_*(NOPE_+VHD_), H_*(NOPE_+VHD_));
    transpose_h<<<dim3(HID_/32, HID_/32), tb>>>(Wo, p_woh, HID_, HID_, HID_);

    // merged qa + kva projection (split fp32 outputs)
    hgemm<2><<<dim3(NQKVP_/128, TOK_/128), 256, SMEM_H>>>(
        p_hsch, p_wqkvh, p_qa, nullptr, p_kvc, KVO_, QR_,
        TOK_, NQKV_, IN_, IN_, IN_, QR_);

    // both rmsnorms in one launch
    rms_both<<<2*TOK_, 256>>>(q_ln, kv_ln);

    // q_b projection (fp32 out, feeds RoPE)
    hgemm<0><<<dim3((H_*QKD_)/128, TOK_/128), 256, SMEM_H>>>(
        p_qah, p_wqbh, p_q, nullptr, nullptr, 0, 0,
        TOK_, H_*QKD_, QR_, QR_, QR_, H_*QKD_);

    // kv_b projection (half out — identical rounding to the old builder cvt)
    hgemm<1><<<dim3((H_*(NOPE_+VHD_))/128, TOK_/128), 256, SMEM_H>>>(
        p_kvnh, p_wkvbh, nullptr, p_kvh, nullptr, 0, 0,
        TOK_, H_*(NOPE_+VHD_), KVR_, KVR_, KVR_, H_*(NOPE_+VHD_));

    // RoPE + assemble
    build_cs<<<(TOK_*32 + 255)/256, 256>>>(pos);
    int nq = BH_ * S_ * QKD_;
    build_q<<<(nq + 255) / 256, 256>>>();
    build_k<<<(nq + 255) / 256, 256>>>();
    int nv = BH_ * VHD_ * S_;
    build_vt<<<(nv + 255) / 256, 256>>>();

    // fused attention
    float scale = 1.f / sqrtf((float)QKD_);
    flash_attn<<<dim3(S_/FBQ, BH_), 256, FSMEM>>>(scale);

    // output projection
    hgemm<0><<<dim3(HID_/128, TOK_/128), 256, SMEM_H>>>(
        p_ctxh, p_woh, out, nullptr, nullptr, 0, 0,
        TOK_, HID_, HID_, HID_, HID_, HID_);
}

// round 12
// speedup vs baseline: 2.3508x; 1.0856x over previous
#include <cuda_runtime.h>
#include <cuda_fp16.h>
#include <math.h>
#include <stdint.h>

// ---------------- problem constants ----------------
#define B_    2
#define S_    2048
#define HID_  2048
#define IN_   4096
#define H_    16
#define NOPE_ 128
#define ROPE_ 64
#define VHD_  128
#define QKD_  192
#define QR_   1536
#define KVR_  512
#define TOK_  (B_*S_)
#define BH_   (B_*H_)
#define EPS_  1e-6f
#define KVO_  (KVR_+ROPE_)   // 576
#define NQKV_ (QR_+KVO_)     // 2112
#define NQKVP_ 2176

// ---------------- scratch ----------------
__device__ float  g_qa  [TOK_*QR_];
__device__ __half g_qah [TOK_*QR_];
__device__ float  g_kvc [TOK_*KVO_];
__device__ __half g_kvnh[TOK_*KVR_];
__device__ __half g_Qfh [BH_*S_*QKD_];
__device__ __half g_Kfh [BH_*S_*QKD_];
__device__ __half g_Vth [BH_*VHD_*S_];             // V^T [bh][d][s]
__device__ __half g_ctxh[TOK_*(H_*VHD_)];
__device__ float  g_cos [TOK_*32];
__device__ float  g_sin [TOK_*32];
__device__ __half g_hsch  [TOK_*IN_];
__device__ __half g_wqkvh [NQKVP_*IN_];
__device__ __half g_wqbh  [(H_*QKD_)*QR_];
__device__ __half g_wkvbh [(H_*(NOPE_+VHD_))*KVR_];
__device__ __half g_woh   [HID_*HID_];

// ---------------- helpers ----------------
__device__ __forceinline__ void mma_f16(float c[4], const uint32_t a[4], const uint32_t b[2]) {
    asm volatile(
        "mma.sync.aligned.m16n8k16.row.col.f32.f16.f16.f32 "
        "{%0,%1,%2,%3}, {%4,%5,%6,%7}, {%8,%9}, {%0,%1,%2,%3};"
        : "+f"(c[0]), "+f"(c[1]), "+f"(c[2]), "+f"(c[3])
        : "r"(a[0]), "r"(a[1]), "r"(a[2]), "r"(a[3]), "r"(b[0]), "r"(b[1]));
}
__device__ __forceinline__ void ldsm_x4(uint32_t& r0, uint32_t& r1, uint32_t& r2, uint32_t& r3,
                                        uint32_t addr) {
    asm volatile("ldmatrix.sync.aligned.m8n8.x4.shared.b16 {%0,%1,%2,%3}, [%4];"
                 : "=r"(r0), "=r"(r1), "=r"(r2), "=r"(r3) : "r"(addr));
}
__device__ __forceinline__ void cp16(uint32_t dst, const void* src) {
    asm volatile("cp.async.cg.shared.global [%0], [%1], 16;\n" :: "r"(dst), "l"(src));
}
__device__ __forceinline__ void cp_commit() {
    asm volatile("cp.async.commit_group;\n" ::: "memory");
}
__device__ __forceinline__ uint32_t h2u(__half2 h) { return *(uint32_t*)&h; }

// ---------------- dense fp16 TB GEMM, ldmatrix mainloop ----------------
// MODE 0: fp32 out
// MODE 2: split fp32 out (cols < nsplit -> C, rest -> C2)
// MODE 3: qb epilogue — RoPE + [bh][s][QKD] half layout into Ch(=g_Qfh)
// MODE 4: kvb epilogue — K_nope -> g_Kfh, V -> g_Vth (transposed)
#define HBK 32
#define HP  40
#define H_STG (128*HP)
#define HSTG  4
#define SMEM_H (HSTG * 2 * H_STG * 2)

template<int MODE>
__global__ __launch_bounds__(256, 2) void hgemm(
    const __half* __restrict__ A, const __half* __restrict__ B,
    float* __restrict__ C, __half* __restrict__ Ch,
    float* __restrict__ C2, int ldc2, int nsplit,
    int M, int N, int K, int lda, int ldb, int ldc)
{
    extern __shared__ __half hsm[];
    __half* Asm = hsm;
    __half* Bsm = hsm + HSTG * H_STG;
    const uint32_t sA32 = (uint32_t)__cvta_generic_to_shared(Asm);
    const uint32_t sB32 = (uint32_t)__cvta_generic_to_shared(Bsm);

    const int nt = K / HBK;
    const int tid  = threadIdx.x;
    const int lane = tid & 31;
    const int g    = lane >> 2;
    const int tig  = lane & 3;
    const int wid  = tid >> 5;
    const int wm   = wid & 1;
    const int wn   = wid >> 1;
    const int rowBase = blockIdx.y * 128;
    const int colBase = blockIdx.x * 128;

    const int r  = tid >> 1;
    const int co = (tid & 1) << 4;
    const __half* Ap = A + (size_t)(rowBase + r) * lda + co;
    const __half* Bp = B + (size_t)(colBase + r) * ldb + co;
    const uint32_t a_dst = sA32 + (uint32_t)(r * HP + co) * 2u;
    const uint32_t b_dst = sB32 + (uint32_t)(r * HP + co) * 2u;

    auto load_stage = [&](int st, int kc) {
        const uint32_t so = (uint32_t)(st * H_STG) * 2u;
        const __half* as = Ap + kc * HBK;
        const __half* bs = Bp + kc * HBK;
        cp16(a_dst + so,      as);
        cp16(a_dst + so + 16, as + 8);
        cp16(b_dst + so,      bs);
        cp16(b_dst + so + 16, bs + 8);
        cp_commit();
    };

    const uint32_t aLB = (uint32_t)(((wm * 64 + (lane & 15)) * HP + (lane >> 4) * 8) * 2);
    const uint32_t bLB = (uint32_t)(((wn * 32 + (lane & 7) + ((lane >> 4) & 1) * 8) * HP
                                     + ((lane >> 3) & 1) * 8) * 2);

    float acc[4][4][4];
    #pragma unroll
    for (int i = 0; i < 4; i++)
        #pragma unroll
        for (int j = 0; j < 4; j++)
            #pragma unroll
            for (int q = 0; q < 4; q++) acc[i][j][q] = 0.f;

    #pragma unroll
    for (int s = 0; s < HSTG - 1; s++) {
        if (s < nt) load_stage(s, s);
        else        cp_commit();
    }

    for (int t = 0; t < nt; t++) {
        asm volatile("cp.async.wait_group 2;\n" ::: "memory");
        __syncthreads();

        const int tn = t + HSTG - 1;
        if (tn < nt) load_stage(tn % HSTG, tn);
        else         cp_commit();

        const uint32_t stoff = (uint32_t)((t % HSTG) * H_STG) * 2u;
        const uint32_t aSt = sA32 + stoff + aLB;
        const uint32_t bSt = sB32 + stoff + bLB;

        #pragma unroll
        for (int ks = 0; ks < 2; ks++) {
            const uint32_t kby = (uint32_t)(ks * 32);
            uint32_t afr[4][4], bfr[4][2];
            #pragma unroll
            for (int fm = 0; fm < 4; fm++)
                ldsm_x4(afr[fm][0], afr[fm][1], afr[fm][2], afr[fm][3],
                        aSt + (uint32_t)(fm * 16 * HP) * 2u + kby);
            #pragma unroll
            for (int fp = 0; fp < 2; fp++)
                ldsm_x4(bfr[2*fp][0], bfr[2*fp][1], bfr[2*fp+1][0], bfr[2*fp+1][1],
                        bSt + (uint32_t)(fp * 16 * HP) * 2u + kby);
            #pragma unroll
            for (int fm = 0; fm < 4; fm++)
                #pragma unroll
                for (int fn = 0; fn < 4; fn++)
                    mma_f16(acc[fm][fn], afr[fm], bfr[fn]);
        }
    }

    #pragma unroll
    for (int fm = 0; fm < 4; fm++) {
        #pragma unroll
        for (int fn = 0; fn < 4; fn++) {
            const int row = rowBase + wm * 64 + fm * 16 + g;
            const int col = colBase + wn * 32 + fn * 8 + tig * 2;   // always even
            if (col >= N) continue;
            const float a0 = acc[fm][fn][0], a1 = acc[fm][fn][1];
            const float a2 = acc[fm][fn][2], a3 = acc[fm][fn][3];

            if (MODE == 0) {
                *(float2*)&C[(size_t)row * ldc + col]       = make_float2(a0, a1);
                *(float2*)&C[(size_t)(row + 8) * ldc + col] = make_float2(a2, a3);
            } else if (MODE == 2) {
                if (col < nsplit) {
                    *(float2*)&C[(size_t)row * ldc + col]       = make_float2(a0, a1);
                    *(float2*)&C[(size_t)(row + 8) * ldc + col] = make_float2(a2, a3);
                } else {
                    const int c2 = col - nsplit;
                    *(float2*)&C2[(size_t)row * ldc2 + c2]       = make_float2(a0, a1);
                    *(float2*)&C2[(size_t)(row + 8) * ldc2 + c2] = make_float2(a2, a3);
                }
            } else if (MODE == 3) {
                // qb: col in [0,3072): h=col/192, d=col%192 (even)
                const int h = col / QKD_, d = col - h * QKD_;
                #pragma unroll
                for (int rr = 0; rr < 2; rr++) {
                    const int tok = row + rr * 8;
                    const int b = tok >> 11, s = tok & (S_-1);
                    __half* dst = Ch + (((size_t)(b * H_ + h) * S_ + s) * QKD_ + d);
                    const float e = rr ? a2 : a0, o = rr ? a3 : a1;
                    __half2 hv;
                    if (d < NOPE_) {
                        hv = __floats2half2_rn(e, o);
                    } else {
                        const int j = (d - NOPE_) >> 1;
                        const float cc = g_cos[tok * 32 + j], ss = g_sin[tok * 32 + j];
                        hv = __floats2half2_rn(e * cc - o * ss, o * cc + e * ss);
                    }
                    *(__half2*)dst = hv;
                }
            } else {  // MODE 4: kvb: col in [0,4096): h=col/256, d=col%256 (even)
                const int h = col >> 8, d = col & 255;
                #pragma unroll
                for (int rr = 0; rr < 2; rr++) {
                    const int tok = row + rr * 8;
                    const int b = tok >> 11, s = tok & (S_-1);
                    const int bh = b * H_ + h;
                    const float e = rr ? a2 : a0, o = rr ? a3 : a1;
                    if (d < NOPE_) {
                        *(__half2*)&g_Kfh[((size_t)bh * S_ + s) * QKD_ + d] =
                            __floats2half2_rn(e, o);
                    } else {
                        const int dd = d - NOPE_;
                        __half* vb = g_Vth + ((size_t)bh * VHD_ + dd) * S_ + s;
                        vb[0]  = __float2half(e);
                        vb[S_] = __float2half(o);
                    }
                }
            }
        }
    }
}

// ---------------- fused flash attention (ldmatrix mainloop) ----------------
#define FBQ 128
#define FBK 64
#define FQP 200
#define FVP 72
#define FQ_SZ (FBQ*FQP)
#define FK_SZ (FBK*FQP)
#define FV_SZ (VHD_*FVP)
#define FSMEM ((FQ_SZ + 2*FK_SZ + 2*FV_SZ) * 2)

__global__ __launch_bounds__(256, 1) void flash_attn(float scale)
{
    extern __shared__ __half fsm[];
    __half* Qs  = fsm;
    __half* Ks0 = Qs + FQ_SZ;
    __half* Vs0 = Ks0 + 2 * FK_SZ;
    const uint32_t sQ = (uint32_t)__cvta_generic_to_shared(Qs);
    const uint32_t sK = (uint32_t)__cvta_generic_to_shared(Ks0);
    const uint32_t sV = (uint32_t)__cvta_generic_to_shared(Vs0);

    const int qt = (int)(gridDim.x - 1 - blockIdx.x);
    const int bh = blockIdx.y;
    const int qbase = qt * FBQ;
    const int tid = threadIdx.x;
    const int wid = tid >> 5, lane = tid & 31, g = lane >> 2, tig = lane & 3;
    const int qr0 = wid * 16;

    const __half* Qg = g_Qfh + ((size_t)bh * S_ + qbase) * QKD_;
    const __half* Kg = g_Kfh + (size_t)bh * S_ * QKD_;
    const __half* Vg = g_Vth + (size_t)bh * VHD_ * S_;

    {
        int r = tid >> 1, off = (tid & 1) * 96;
        const __half* src = Qg + (size_t)r * QKD_ + off;
        uint32_t dst = sQ + (uint32_t)(r * FQP + off) * 2u;
        #pragma unroll
        for (int c = 0; c < 12; c++) cp16(dst + c * 16, src + c * 8);
    }
    auto loadKV = [&](int st, int kt) {
        const int kbase = kt * FBK;
        {   int r = tid >> 2, off = (tid & 3) * 48;
            const __half* src = Kg + (size_t)(kbase + r) * QKD_ + off;
            uint32_t dst = sK + (uint32_t)(st * FK_SZ + r * FQP + off) * 2u;
            #pragma unroll
            for (int c = 0; c < 6; c++) cp16(dst + c * 16, src + c * 8);
        }
        {   int r = tid >> 1, off = (tid & 1) * 32;
            const __half* src = Vg + (size_t)r * S_ + kbase + off;
            uint32_t dst = sV + (uint32_t)(st * FV_SZ + r * FVP + off) * 2u;
            #pragma unroll
            for (int c = 0; c < 4; c++) cp16(dst + c * 16, src + c * 8);
        }
        cp_commit();
    };

    const int ktmax = (qbase + FBQ - 1) / FBK;
    loadKV(0, 0);

    float oacc[16][4];
    #pragma unroll
    for (int i = 0; i < 16; i++)
        #pragma unroll
        for (int j = 0; j < 4; j++) oacc[i][j] = 0.f;
    float sm0 = -1e30f, sm1 = -1e30f, l0 = 0.f, l1 = 0.f;

    const int row0 = qbase + qr0 + g;
    const int row1 = row0 + 8;

    const uint32_t aQB = sQ + (uint32_t)(((qr0 + (lane & 15)) * FQP + (lane >> 4) * 8) * 2);
    const uint32_t bRow = (uint32_t)((lane & 7) + ((lane >> 4) & 1) * 8);
    const uint32_t bCol = (uint32_t)(((lane >> 3) & 1) * 8);
    const uint32_t bKB = (uint32_t)((bRow * FQP + bCol) * 2);
    const uint32_t bVB = (uint32_t)((bRow * FVP + bCol) * 2);

    for (int kt = 0; kt <= ktmax; kt++) {
        const int st = kt & 1;
        if (kt < ktmax) {
            loadKV(st ^ 1, kt + 1);
            asm volatile("cp.async.wait_group 1;\n" ::: "memory");
        } else {
            asm volatile("cp.async.wait_group 0;\n" ::: "memory");
        }
        __syncthreads();

        const int kbase = kt * FBK;
        if (kbase <= qbase + qr0 + 15) {
            const uint32_t kSt = sK + (uint32_t)(st * FK_SZ) * 2u + bKB;
            const uint32_t vSt = sV + (uint32_t)(st * FV_SZ) * 2u + bVB;

            float sacc[8][4];
            #pragma unroll
            for (int nb = 0; nb < 8; nb++)
                #pragma unroll
                for (int j = 0; j < 4; j++) sacc[nb][j] = 0.f;

            #pragma unroll
            for (int kc = 0; kc < 12; kc++) {
                const uint32_t kby = (uint32_t)(kc * 32);
                uint32_t a[4];
                ldsm_x4(a[0], a[1], a[2], a[3], aQB + kby);
                uint32_t b[8][2];
                #pragma unroll
                for (int np = 0; np < 4; np++)
                    ldsm_x4(b[2*np][0], b[2*np][1], b[2*np+1][0], b[2*np+1][1],
                            kSt + (uint32_t)(np * 16 * FQP) * 2u + kby);
                #pragma unroll
                for (int nb = 0; nb < 8; nb++)
                    mma_f16(sacc[nb], a, b[nb]);
            }

            const bool need_mask = (kbase + FBK - 1) > (qbase + qr0);
            #pragma unroll
            for (int nb = 0; nb < 8; nb++) {
                const int c0 = kbase + nb * 8 + 2 * tig, c1 = c0 + 1;
                sacc[nb][0] *= scale; sacc[nb][1] *= scale;
                sacc[nb][2] *= scale; sacc[nb][3] *= scale;
                if (need_mask) {
                    if (c0 > row0) sacc[nb][0] = -1e30f;
                    if (c1 > row0) sacc[nb][1] = -1e30f;
                    if (c0 > row1) sacc[nb][2] = -1e30f;
                    if (c1 > row1) sacc[nb][3] = -1e30f;
                }
            }

            float mx0 = -1e30f, mx1 = -1e30f;
            #pragma unroll
            for (int nb = 0; nb < 8; nb++) {
                mx0 = fmaxf(mx0, fmaxf(sacc[nb][0], sacc[nb][1]));
                mx1 = fmaxf(mx1, fmaxf(sacc[nb][2], sacc[nb][3]));
            }
            mx0 = fmaxf(mx0, __shfl_xor_sync(0xFFFFFFFFu, mx0, 1));
            mx0 = fmaxf(mx0, __shfl_xor_sync(0xFFFFFFFFu, mx0, 2));
            mx1 = fmaxf(mx1, __shfl_xor_sync(0xFFFFFFFFu, mx1, 1));
            mx1 = fmaxf(mx1, __shfl_xor_sync(0xFFFFFFFFu, mx1, 2));

            const float mn0 = fmaxf(sm0, mx0), mn1 = fmaxf(sm1, mx1);
            const float al0 = __expf(sm0 - mn0), al1 = __expf(sm1 - mn1);
            sm0 = mn0; sm1 = mn1;

            uint32_t pA[8], pB[8];
            float ps0 = 0.f, ps1 = 0.f;
            #pragma unroll
            for (int nb = 0; nb < 8; nb++) {
                const float e0 = __expf(sacc[nb][0] - mn0);
                const float e1 = __expf(sacc[nb][1] - mn0);
                const float e2 = __expf(sacc[nb][2] - mn1);
                const float e3 = __expf(sacc[nb][3] - mn1);
                ps0 += e0 + e1; ps1 += e2 + e3;
                pA[nb] = h2u(__floats2half2_rn(e0, e1));
                pB[nb] = h2u(__floats2half2_rn(e2, e3));
            }
            l0 = l0 * al0 + ps0;
            l1 = l1 * al1 + ps1;

            #pragma unroll
            for (int nb2 = 0; nb2 < 16; nb2++) {
                oacc[nb2][0] *= al0; oacc[nb2][1] *= al0;
                oacc[nb2][2] *= al1; oacc[nb2][3] *= al1;
            }

            #pragma unroll
            for (int kc = 0; kc < 4; kc++) {
                uint32_t a[4] = { pA[2*kc], pB[2*kc], pA[2*kc+1], pB[2*kc+1] };
                const uint32_t kby = (uint32_t)(kc * 32);
                uint32_t bv[16][2];
                #pragma unroll
                for (int np = 0; np < 8; np++)
                    ldsm_x4(bv[2*np][0], bv[2*np][1], bv[2*np+1][0], bv[2*np+1][1],
                            vSt + (uint32_t)(np * 16 * FVP) * 2u + kby);
                #pragma unroll
                for (int nb2 = 0; nb2 < 16; nb2++)
                    mma_f16(oacc[nb2], a, bv[nb2]);
            }
        }
        __syncthreads();
    }

    l0 += __shfl_xor_sync(0xFFFFFFFFu, l0, 1);
    l0 += __shfl_xor_sync(0xFFFFFFFFu, l0, 2);
    l1 += __shfl_xor_sync(0xFFFFFFFFu, l1, 1);
    l1 += __shfl_xor_sync(0xFFFFFFFFu, l1, 2);
    const float inv0 = 1.f / l0, inv1 = 1.f / l1;

    const int b = bh / H_, h = bh % H_;
    __half* out0 = g_ctxh + (size_t)(b * S_ + row0) * (H_*VHD_) + h * VHD_;
    __half* out1 = out0 + (size_t)8 * (H_*VHD_);
    #pragma unroll
    for (int nb2 = 0; nb2 < 16; nb2++) {
        const int d = nb2 * 8 + 2 * tig;
        *(__half2*)(out0 + d) = __floats2half2_rn(oacc[nb2][0] * inv0, oacc[nb2][1] * inv0);
        *(__half2*)(out1 + d) = __floats2half2_rn(oacc[nb2][2] * inv1, oacc[nb2][3] * inv1);
    }
}

// ---------------- converts ----------------
__global__ void cvt_h(const float* __restrict__ src, __half* __restrict__ dst, int n4) {
    int i = blockIdx.x * blockDim.x + threadIdx.x;
    if (i >= n4) return;
    float4 v = ((const float4*)src)[i];
    ((__half2*)dst)[2*i]   = __floats2half2_rn(v.x, v.y);
    ((__half2*)dst)[2*i+1] = __floats2half2_rn(v.z, v.w);
}

__global__ void transpose_h(const float* __restrict__ src, __half* __restrict__ dst,
                            int K, int N, int Npad)
{
    __shared__ float tile[32][33];
    const int k0 = blockIdx.y * 32, n0 = blockIdx.x * 32;
    const int tx = threadIdx.x, ty = threadIdx.y;
    #pragma unroll
    for (int i = ty; i < 32; i += 8) {
        int k = k0 + i, n = n0 + tx;
        tile[i][tx] = (k < K && n < N) ? src[(size_t)k * N + n] : 0.f;
    }
    __syncthreads();
    #pragma unroll
    for (int i = ty; i < 32; i += 8) {
        int n = n0 + i, k = k0 + tx;
        if (n < Npad && k < K) dst[(size_t)n * K + k] = __float2half(tile[tx][i]);
    }
}

// ---------------- fused rmsnorm ----------------
__device__ __forceinline__ float block_reduce_sum(float v, float* sbuf) {
    int tid = threadIdx.x;
    sbuf[tid] = v; __syncthreads();
    #pragma unroll
    for (int s = 128; s > 0; s >>= 1) {
        if (tid < s) sbuf[tid] = sbuf[tid] + sbuf[tid + s];
        __syncthreads();
    }
    float r = sbuf[0]; __syncthreads();
    return r;
}

__global__ __launch_bounds__(256) void rms_both(const float* __restrict__ q_ln,
                                                const float* __restrict__ kv_ln)
{
    __shared__ float sbuf[256];
    const int row = blockIdx.x;
    const float* xr;
    const float* w;
    __half* yr;
    int n;
    if (row < TOK_) {
        xr = g_qa + (size_t)row * QR_; w = q_ln; yr = g_qah + (size_t)row * QR_; n = QR_;
    } else {
        int r = row - TOK_;
        xr = g_kvc + (size_t)r * KVO_; w = kv_ln; yr = g_kvnh + (size_t)r * KVR_; n = KVR_;
    }
    float acc = 0.f;
    for (int j = threadIdx.x; j < n; j += 256) { float v = xr[j]; acc += v * v; }
    float tot = block_reduce_sum(acc, sbuf);
    float scale = rsqrtf(tot / (float)n + EPS_);
    for (int j = threadIdx.x; j < n; j += 256) yr[j] = __float2half(xr[j] * scale * w[j]);
}

// ---------------- RoPE table + K-rope broadcast ----------------
__global__ void build_cs(const int* __restrict__ pos) {
    int idx = blockIdx.x * blockDim.x + threadIdx.x;
    if (idx >= TOK_ * 32) return;
    int j = idx & 31, tok = idx >> 5;
    float inv = powf(10000.f, -((float)(2 * j)) / 64.f);
    float ang = (float)pos[tok] * inv;
    g_cos[idx] = cosf(ang);
    g_sin[idx] = sinf(ang);
}

// write g_Kfh[bh][s][128:192] for all bh from kvc rope cols
__global__ void rope_k() {
    int idx = blockIdx.x * blockDim.x + threadIdx.x;       // BH_*S_*32 pairs
    if (idx >= BH_ * S_ * 32) return;
    int j  = idx & 31;
    int r  = idx >> 5;
    int s  = r % S_;
    int bh = r / S_;
    int b  = bh / H_;
    int tok = b * S_ + s;
    const float* pb = g_kvc + (size_t)tok * KVO_ + KVR_;
    float c = g_cos[tok * 32 + j], sn = g_sin[tok * 32 + j];
    float ev = pb[2*j], ov = pb[2*j + 1];
    *(__half2*)&g_Kfh[((size_t)bh * S_ + s) * QKD_ + NOPE_ + 2*j] =
        __floats2half2_rn(ev * c - ov * sn, ov * c + ev * sn);
}

// ---------------- launcher ----------------
extern "C" void kernel_launch(void* const* d_in, const int* in_sizes, int n_in,
                              void* d_out, int out_size)
{
    const float* hs    = (const float*)d_in[0];
    const float* Wq_a  = (const float*)d_in[1];
    const float* q_ln  = (const float*)d_in[2];
    const float* Wq_b  = (const float*)d_in[3];
    const float* Wkv_a = (const float*)d_in[4];
    const float* kv_ln = (const float*)d_in[5];
    const float* Wkv_b = (const float*)d_in[6];
    const float* Wo    = (const float*)d_in[7];
    const int*   pos   = (const int*)  d_in[8];
    float* out = (float*)d_out;

    float *p_qa, *p_kvc;
    __half *p_qah, *p_kvnh, *p_Qfh, *p_ctxh;
    __half *p_hsch, *p_wqkvh, *p_wqbh, *p_wkvbh, *p_woh;
    cudaGetSymbolAddress((void**)&p_qa,    g_qa);
    cudaGetSymbolAddress((void**)&p_qah,   g_qah);
    cudaGetSymbolAddress((void**)&p_kvc,   g_kvc);
    cudaGetSymbolAddress((void**)&p_kvnh,  g_kvnh);
    cudaGetSymbolAddress((void**)&p_Qfh,   g_Qfh);
    cudaGetSymbolAddress((void**)&p_ctxh,  g_ctxh);
    cudaGetSymbolAddress((void**)&p_hsch,  g_hsch);
    cudaGetSymbolAddress((void**)&p_wqkvh, g_wqkvh);
    cudaGetSymbolAddress((void**)&p_wqbh,  g_wqbh);
    cudaGetSymbolAddress((void**)&p_wkvbh, g_wkvbh);
    cudaGetSymbolAddress((void**)&p_woh,   g_woh);

    static bool attr_done = false;
    if (!attr_done) {
        cudaFuncSetAttribute(hgemm<0>, cudaFuncAttributeMaxDynamicSharedMemorySize, SMEM_H);
        cudaFuncSetAttribute(hgemm<2>, cudaFuncAttributeMaxDynamicSharedMemorySize, SMEM_H);
        cudaFuncSetAttribute(hgemm<3>, cudaFuncAttributeMaxDynamicSharedMemorySize, SMEM_H);
        cudaFuncSetAttribute(hgemm<4>, cudaFuncAttributeMaxDynamicSharedMemorySize, SMEM_H);
        cudaFuncSetAttribute(flash_attn, cudaFuncAttributeMaxDynamicSharedMemorySize, FSMEM);
        attr_done = true;
    }

    // converts
    cvt_h<<<(TOK_*IN_/4 + 255)/256, 256>>>(hs, p_hsch, TOK_*IN_/4);
    dim3 tb(32, 8);
    transpose_h<<<dim3(QR_/32, IN_/32), tb>>>(Wq_a, p_wqkvh, IN_, QR_, QR_);
    transpose_h<<<dim3((KVO_+31)/32, IN_/32), tb>>>(Wkv_a, p_wqkvh + (size_t)QR_*IN_,
                                                    IN_, KVO_, KVO_);
    transpose_h<<<dim3((H_*QKD_)/32, QR_/32), tb>>>(Wq_b, p_wqbh, QR_, H_*QKD_, H_*QKD_);
    transpose_h<<<dim3((H_*(NOPE_+VHD_))/32, KVR_/32), tb>>>(Wkv_b, p_wkvbh,
                                                             KVR_, H_*(NOPE_+VHD_), H_*(NOPE_+VHD_));
    transpose_h<<<dim3(HID_/32, HID_/32), tb>>>(Wo, p_woh, HID_, HID_, HID_);
    build_cs<<<(TOK_*32 + 255)/256, 256>>>(pos);

    // merged qa + kva projection
    hgemm<2><<<dim3(NQKVP_/128, TOK_/128), 256, SMEM_H>>>(
        p_hsch, p_wqkvh, p_qa, nullptr, p_kvc, KVO_, QR_,
        TOK_, NQKV_, IN_, IN_, IN_, QR_);

    rms_both<<<2*TOK_, 256>>>(q_ln, kv_ln);
    rope_k<<<(BH_*S_*32 + 255)/256, 256>>>();   // needs only kvc + cos/sin

    // qb projection with fused RoPE + layout (writes g_Qfh)
    hgemm<3><<<dim3((H_*QKD_)/128, TOK_/128), 256, SMEM_H>>>(
        p_qah, p_wqbh, nullptr, p_Qfh, nullptr, 0, 0,
        TOK_, H_*QKD_, QR_, QR_, QR_, H_*QKD_);

    // kvb projection with fused K/V scatter (writes g_Kfh nope + g_Vth)
    hgemm<4><<<dim3((H_*(NOPE_+VHD_))/128, TOK_/128), 256, SMEM_H>>>(
        p_kvnh, p_wkvbh, nullptr, nullptr, nullptr, 0, 0,
        TOK_, H_*(NOPE_+VHD_), KVR_, KVR_, KVR_, H_*(NOPE_+VHD_));

    // fused attention
    float scale = 1.f / sqrtf((float)QKD_);
    flash_attn<<<dim3(S_/FBQ, BH_), 256, FSMEM>>>(scale);

    // output projection
    hgemm<0><<<dim3(HID_/128, TOK_/128), 256, SMEM_H>>>(
        p_ctxh, p_woh, out, nullptr, nullptr, 0, 0,
        TOK_, HID_, HID_, HID_, HID_, HID_);
}